// round 13
// baseline (speedup 1.0000x reference)
#include <cuda_runtime.h>
#include <cuda_bf16.h>
#include <cstdint>

#define BB 8
#define TT 2048
#define DD 1024
#define QD 128

// ---------------- global scratch ----------------
__device__ __nv_bfloat16 g_x_hi[(size_t)BB*TT*DD];
__device__ __nv_bfloat16 g_x_lo[(size_t)BB*TT*DD];
__device__ __nv_bfloat16 g_w_hi[3*QD*DD];
__device__ __nv_bfloat16 g_w_lo[3*QD*DD];
__device__ __nv_bfloat16 g_q_hi[BB*TT*QD];
__device__ __nv_bfloat16 g_q_lo[BB*TT*QD];
__device__ __nv_bfloat16 g_k_hi[BB*TT*QD];
__device__ __nv_bfloat16 g_k_lo[BB*TT*QD];
__device__ __nv_bfloat16 g_v_hi[BB*TT*QD];           // row-major [b][t][d]
__device__ __nv_bfloat16 g_v_lo[BB*TT*QD];
__device__ float g_mask[BB*TT];
__device__ int   g_mask_kind;

// ---------------- helpers ----------------
__device__ __forceinline__ uint32_t smem_u32(const void* p) {
    uint32_t a;
    asm("{ .reg .u64 t; cvta.to.shared.u64 t, %1; cvt.u32.u64 %0, t; }" : "=r"(a) : "l"(p));
    return a;
}
__device__ __forceinline__ uint32_t pk(__nv_bfloat16 a, __nv_bfloat16 b) {
    return (uint32_t)__bfloat16_as_ushort(a) | ((uint32_t)__bfloat16_as_ushort(b) << 16);
}
__device__ __forceinline__ void split2(float a, float b, uint32_t& h, uint32_t& l) {
    __nv_bfloat16 ha = __float2bfloat16_rn(a);
    __nv_bfloat16 hb = __float2bfloat16_rn(b);
    __nv_bfloat16 la = __float2bfloat16_rn(a - __bfloat162float(ha));
    __nv_bfloat16 lb = __float2bfloat16_rn(b - __bfloat162float(hb));
    h = pk(ha, hb); l = pk(la, lb);
}
__device__ __forceinline__ void ldm4(uint32_t r[4], uint32_t a) {
    asm volatile("ldmatrix.sync.aligned.m8n8.x4.shared.b16 {%0,%1,%2,%3}, [%4];"
        : "=r"(r[0]), "=r"(r[1]), "=r"(r[2]), "=r"(r[3]) : "r"(a));
}
__device__ __forceinline__ void ldm4t(uint32_t r[4], uint32_t a) {
    asm volatile("ldmatrix.sync.aligned.m8n8.x4.trans.shared.b16 {%0,%1,%2,%3}, [%4];"
        : "=r"(r[0]), "=r"(r[1]), "=r"(r[2]), "=r"(r[3]) : "r"(a));
}
__device__ __forceinline__ void mma_bf16(float* c, const uint32_t* a, const uint32_t* b) {
    asm volatile("mma.sync.aligned.m16n8k16.row.col.f32.bf16.bf16.f32 "
        "{%0,%1,%2,%3}, {%4,%5,%6,%7}, {%8,%9}, {%0,%1,%2,%3};"
        : "+f"(c[0]), "+f"(c[1]), "+f"(c[2]), "+f"(c[3])
        : "r"(a[0]), "r"(a[1]), "r"(a[2]), "r"(a[3]), "r"(b[0]), "r"(b[1]));
}
__device__ __forceinline__ void cp16(uint32_t dst, const void* src) {
    asm volatile("cp.async.cg.shared.global [%0], [%1], 16;"
        :: "r"(dst), "l"(__cvta_generic_to_global(src)) : "memory");
}
#define CP_COMMIT() asm volatile("cp.async.commit_group;" ::: "memory")
#define CP_WAIT(n)  asm volatile("cp.async.wait_group %0;" :: "n"(n) : "memory")

// ---------------- mask canonicalization (proven) ----------------
__global__ void mask_sniff(const uint8_t* __restrict__ m) {
    __shared__ unsigned r1[256], r3[256];
    unsigned o1 = 0, o3 = 0;
    const uint32_t* w = (const uint32_t*)m;
    for (int i = threadIdx.x; i < (BB*TT)/4; i += 256) {
        uint32_t v = w[i];
        o1 |= (v >> 8) & 0xFFu; o3 |= (v >> 24) & 0xFFu;
    }
    r1[threadIdx.x] = o1; r3[threadIdx.x] = o3;
    __syncthreads();
    for (int s = 128; s; s >>= 1) {
        if (threadIdx.x < s) { r1[threadIdx.x] |= r1[threadIdx.x+s]; r3[threadIdx.x] |= r3[threadIdx.x+s]; }
        __syncthreads();
    }
    if (threadIdx.x == 0) g_mask_kind = r1[0] ? 1 : (r3[0] ? 2 : 0);
}
__global__ void mask_expand(const void* __restrict__ m) {
    int s = blockIdx.x * 256 + threadIdx.x;
    if (s >= BB*TT) return;
    int kind = g_mask_kind;
    float v;
    if (kind == 1)      v = ((const uint8_t*)m)[s] ? 1.0f : 0.0f;
    else if (kind == 2) v = (((const float*)m)[s] != 0.0f) ? 1.0f : 0.0f;
    else                v = ((const int*)m)[s] ? 1.0f : 0.0f;
    g_mask[s] = v;
}

// ---------------- prep: split x and W into bf16 hi/lo ----------------
__global__ __launch_bounds__(256) void prep_kernel(
    const float* __restrict__ x,  const float* __restrict__ Wq,
    const float* __restrict__ Wk, const float* __restrict__ Wv)
{
    const int y = blockIdx.y;
    const size_t i = (size_t)blockIdx.x * 256 + threadIdx.x;
    const float* src; __nv_bfloat16 *dh, *dl; size_t n4;
    if (y == 0) { src = x; dh = g_x_hi; dl = g_x_lo; n4 = (size_t)BB*TT*DD/4; }
    else {
        src = (y == 1) ? Wq : ((y == 2) ? Wk : Wv);
        dh = g_w_hi + (size_t)(y-1)*QD*DD; dl = g_w_lo + (size_t)(y-1)*QD*DD;
        n4 = (size_t)QD*DD/4;
    }
    if (i >= n4) return;
    float4 v = ((const float4*)src)[i];
    uint32_t h01, l01, h23, l23;
    split2(v.x, v.y, h01, l01);
    split2(v.z, v.w, h23, l23);
    ((uint2*)dh)[i] = make_uint2(h01, h23);
    ((uint2*)dl)[i] = make_uint2(l01, l23);
}

// ---------------- projection GEMM (round-11 best: 256 thr, cp.async 2-stage) ----------------
#define PJ_AH 0
#define PJ_AL 16384
#define PJ_BH 32768
#define PJ_BL 49152
#define PJ_STAGE 65536
#define PJ_SMEM (2*PJ_STAGE + 1024)

__global__ __launch_bounds__(256, 1) void proj_kernel()
{
    extern __shared__ char smraw[];
    char* sp = (char*)(((uintptr_t)smraw + 1023) & ~(uintptr_t)1023);
    uint32_t sb = smem_u32(sp);
    const int tid = threadIdx.x, lane = tid & 31, w = tid >> 5;
    const int m0 = blockIdx.x * 128, z = blockIdx.y;
    const int wm = w & 3, wn = w >> 2;
    const int mrow0 = wm * 32, ncol0 = wn * 64;

    const __nv_bfloat16* xh = g_x_hi;
    const __nv_bfloat16* xl = g_x_lo;
    const __nv_bfloat16* wh = g_w_hi + (size_t)z*QD*DD;
    const __nv_bfloat16* wl = g_w_lo + (size_t)z*QD*DD;

    const int mat = lane >> 3;
    const uint32_t xorv = (uint32_t)(lane & 7) << 4;
    const int rA = (mat & 1) * 8 + (lane & 7);
    const int cA = (mat >> 1) * 16;
    const int rB = (mat >> 1) * 8 + (lane & 7);
    const int cB = (mat & 1) * 16;

    const int srow = tid >> 3, sci = tid & 7;
    float C[2][8][4] = {};

    #define PJ_STAGE_CHUNK(c) do {                                              \
        const int _k0 = (c) * 64;                                               \
        uint32_t _bb = sb + (uint32_t)((c) & 1) * PJ_STAGE;                     \
        _Pragma("unroll")                                                       \
        for (int _r = 0; _r < 4; _r++) {                                        \
            int _row = srow + _r * 32;                                          \
            uint32_t _doff = (uint32_t)_row * 128 +                             \
                (((uint32_t)sci * 16) ^ ((uint32_t)(_row & 7) << 4));           \
            const size_t _go = (size_t)(m0 + _row) * DD + _k0 + sci * 8;        \
            const size_t _gw = (size_t)_row * DD + _k0 + sci * 8;               \
            cp16(_bb + PJ_AH + _doff, xh + _go);                                \
            cp16(_bb + PJ_AL + _doff, xl + _go);                                \
            cp16(_bb + PJ_BH + _doff, wh + _gw);                                \
            cp16(_bb + PJ_BL + _doff, wl + _gw);                                \
        } } while (0)

    PJ_STAGE_CHUNK(0); CP_COMMIT();

    for (int c = 0; c < 16; c++) {
        if (c + 1 < 16) { PJ_STAGE_CHUNK(c + 1); CP_COMMIT(); CP_WAIT(1); }
        else            { CP_WAIT(0); }
        __syncthreads();
        const uint32_t bb = sb + (uint32_t)(c & 1) * PJ_STAGE;

        #pragma unroll
        for (int ks = 0; ks < 4; ks++) {
            const int k0 = ks * 16;
            uint32_t ah[2][4], al[2][4];
            #pragma unroll
            for (int mt = 0; mt < 2; mt++) {
                uint32_t aoff = (uint32_t)(mrow0 + mt*16 + rA) * 128 + (((uint32_t)(k0*2 + cA)) ^ xorv);
                ldm4(ah[mt], bb + PJ_AH + aoff);
                ldm4(al[mt], bb + PJ_AL + aoff);
            }
            #pragma unroll
            for (int nt2 = 0; nt2 < 4; nt2++) {
                const int n0 = ncol0 + nt2 * 16;
                uint32_t boff = (uint32_t)(n0 + rB) * 128 + (((uint32_t)(k0*2 + cB)) ^ xorv);
                uint32_t bh[4], bl[4];
                ldm4(bh, bb + PJ_BH + boff);
                ldm4(bl, bb + PJ_BL + boff);
                #pragma unroll
                for (int mt = 0; mt < 2; mt++) {
                    mma_bf16(C[mt][nt2*2],   ah[mt], bh);
                    mma_bf16(C[mt][nt2*2],   ah[mt], bl);
                    mma_bf16(C[mt][nt2*2],   al[mt], bh);
                    mma_bf16(C[mt][nt2*2+1], ah[mt], bh + 2);
                    mma_bf16(C[mt][nt2*2+1], ah[mt], bl + 2);
                    mma_bf16(C[mt][nt2*2+1], al[mt], bh + 2);
                }
            }
        }
        __syncthreads();
    }

    __nv_bfloat16 *dh, *dl;
    if (z == 0)      { dh = g_q_hi; dl = g_q_lo; }
    else if (z == 1) { dh = g_k_hi; dl = g_k_lo; }
    else             { dh = g_v_hi; dl = g_v_lo; }
    const int r = lane >> 2, c2 = 2 * (lane & 3);
    #pragma unroll
    for (int mt = 0; mt < 2; mt++) {
        #pragma unroll
        for (int nt = 0; nt < 8; nt++) {
            int cc = ncol0 + nt * 8 + c2;
            size_t mg0 = (size_t)(m0 + mrow0 + mt*16 + r);
            uint32_t h, l;
            split2(C[mt][nt][0], C[mt][nt][1], h, l);
            *(uint32_t*)(dh + mg0*QD + cc) = h;
            *(uint32_t*)(dl + mg0*QD + cc) = l;
            split2(C[mt][nt][2], C[mt][nt][3], h, l);
            *(uint32_t*)(dh + (mg0+8)*QD + cc) = h;
            *(uint32_t*)(dl + (mg0+8)*QD + cc) = l;
        }
    }
}

// ---------------- flash attention v3: 64 q-rows/CTA, 4 warps, 2 CTAs/SM ----------------
// grid (32 q-tiles, 8 batches) = 256 CTAs -> single wave on 296 slots.
// Each warp owns 16 q-rows x ALL 64 keys of a tile: row-private softmax,
// no cross-warp reductions, no O merge. Phase-pipelined cp.async as before.
#define A3_QH 0
#define A3_QL 16384
#define A3_KH 32768
#define A3_KL 49152
#define A3_VH 65536
#define A3_VL 81920
#define A3_MK 98304
#define A3_SMEM (98304 + 256 + 2048)

__global__ __launch_bounds__(256, 2) void attn_kernel(float* __restrict__ out)
{
    extern __shared__ char smraw[];
    char* sp = (char*)(((uintptr_t)smraw + 1023) & ~(uintptr_t)1023);
    uint32_t sb = smem_u32(sp);
    float* mkS = (float*)(sp + A3_MK);
    const int tid = threadIdx.x, lane = tid & 31, w = tid >> 5;  // w in 0..7
    const int b = blockIdx.y, t0 = blockIdx.x * 64;
    const int m0w = (w & 3) * 16;   // 4 warps x 16 rows (w>=4 unused rows alias safely: blockDim 256 = 8 warps? -> we launch 256 thr = 8 warps; use all 8: w&3 row group, but then two warps share rows -> NO. Launch 128 thr instead.)

    // NOTE: kernel is launched with 128 threads (4 warps). See launch config.

    const int mat = lane >> 3;
    const uint32_t xorv = (uint32_t)(lane & 7) << 4;
    const int rA = (mat & 1) * 8 + (lane & 7);
    const int cA = (mat >> 1) * 16;
    const int rB = (mat >> 1) * 8 + (lane & 7);
    const int cB = (mat & 1) * 16;

    const int srow = tid >> 4, sci = tid & 15;   // 128 thr: srow 0..7

    #define A3_ISSUE_K(it) do {                                                 \
        const int _s0 = (it) * 64;                                              \
        _Pragma("unroll")                                                       \
        for (int _r = 0; _r < 8; _r++) {                                        \
            int _row = srow + _r * 8;                                           \
            uint32_t _doff = (uint32_t)_row * 256 +                             \
                (((uint32_t)sci * 16) ^ ((uint32_t)(_row & 7) << 4));           \
            const size_t _g = (size_t)(b*TT + _s0 + _row) * QD + sci * 8;       \
            cp16(sb + A3_KH + _doff, g_k_hi + _g);                              \
            cp16(sb + A3_KL + _doff, g_k_lo + _g);                              \
        }                                                                       \
        if (tid < 16) cp16(sb + A3_MK + tid*16, g_mask + b*TT + _s0 + tid*4);   \
    } while (0)

    #define A3_ISSUE_V(it) do {                                                 \
        const int _s0 = (it) * 64;                                              \
        _Pragma("unroll")                                                       \
        for (int _r = 0; _r < 8; _r++) {                                        \
            int _row = srow + _r * 8;                                           \
            uint32_t _doff = (uint32_t)_row * 256 +                             \
                (((uint32_t)sci * 16) ^ ((uint32_t)(_row & 7) << 4));           \
            const size_t _g = (size_t)(b*TT + _s0 + _row) * QD + sci * 8;       \
            cp16(sb + A3_VH + _doff, g_v_hi + _g);                              \
            cp16(sb + A3_VL + _doff, g_v_lo + _g);                              \
        } } while (0)

    A3_ISSUE_K(0); CP_COMMIT();
    A3_ISSUE_V(0); CP_COMMIT();

    // stage Q tile 64x128 hi/lo (128 threads, 8 passes over 1024 uint4)
    {
        const uint4* qh = (const uint4*)(g_q_hi + (size_t)(b*TT + t0) * QD);
        const uint4* ql = (const uint4*)(g_q_lo + (size_t)(b*TT + t0) * QD);
        #pragma unroll
        for (int r = 0; r < 8; r++) {
            int idx = tid + r * 128;
            int row = idx >> 4;
            uint32_t cb = (uint32_t)(idx & 15) * 16;
            uint32_t doff = (uint32_t)row * 256 + (cb ^ ((uint32_t)(row & 7) << 4));
            *(uint4*)(sp + A3_QH + doff) = qh[idx];
            *(uint4*)(sp + A3_QL + doff) = ql[idx];
        }
    }

    float O[16][4] = {};
    float m0r = -1.0e30f, m1r = -1.0e30f, s0r = 0.0f, s1r = 0.0f;
    const int c2 = 2 * (lane & 3);

    for (int it = 0; it < 32; it++) {
        CP_WAIT(1);                  // K(it)+mask ready
        __syncthreads();

        // S = Q(16x128) K^T (64 keys) per warp
        float S[8][4] = {};
        #pragma unroll
        for (int ks = 0; ks < 8; ks++) {
            const int k0 = ks * 16;
            uint32_t aqh[4], aql[4];
            uint32_t aoff = (uint32_t)(m0w + rA) * 256 + (((uint32_t)(k0*2 + cA)) ^ xorv);
            ldm4(aqh, sb + A3_QH + aoff);
            ldm4(aql, sb + A3_QL + aoff);
            #pragma unroll
            for (int nt2 = 0; nt2 < 4; nt2++) {
                const int n0 = nt2 * 16;
                uint32_t boff = (uint32_t)(n0 + rB) * 256 + (((uint32_t)(k0*2 + cB)) ^ xorv);
                uint32_t bh[4], bl[4];
                ldm4(bh, sb + A3_KH + boff);
                ldm4(bl, sb + A3_KL + boff);
                mma_bf16(S[nt2*2],   aqh, bh);
                mma_bf16(S[nt2*2],   aqh, bl);
                mma_bf16(S[nt2*2],   aql, bh);
                mma_bf16(S[nt2*2+1], aqh, bh + 2);
                mma_bf16(S[nt2*2+1], aqh, bl + 2);
                mma_bf16(S[nt2*2+1], aql, bh + 2);
            }
        }

        // masked online softmax (row-private: rows lane>>2 and +8)
        float mx0 = -3.0e38f, mx1 = -3.0e38f;
        #pragma unroll
        for (int nt = 0; nt < 8; nt++) {
            float k0m = mkS[nt*8 + c2], k1m = mkS[nt*8 + c2 + 1];
            S[nt][0] = (k0m != 0.0f) ? S[nt][0] : -3.0e38f;
            S[nt][1] = (k1m != 0.0f) ? S[nt][1] : -3.0e38f;
            S[nt][2] = (k0m != 0.0f) ? S[nt][2] : -3.0e38f;
            S[nt][3] = (k1m != 0.0f) ? S[nt][3] : -3.0e38f;
            mx0 = fmaxf(mx0, fmaxf(S[nt][0], S[nt][1]));
            mx1 = fmaxf(mx1, fmaxf(S[nt][2], S[nt][3]));
        }
        mx0 = fmaxf(mx0, __shfl_xor_sync(0xffffffffu, mx0, 1));
        mx0 = fmaxf(mx0, __shfl_xor_sync(0xffffffffu, mx0, 2));
        mx1 = fmaxf(mx1, __shfl_xor_sync(0xffffffffu, mx1, 1));
        mx1 = fmaxf(mx1, __shfl_xor_sync(0xffffffffu, mx1, 2));
        float mn0 = fmaxf(m0r, mx0), mn1 = fmaxf(m1r, mx1);
        float sc0 = __expf(m0r - mn0), sc1 = __expf(m1r - mn1);
        float sum0 = 0.0f, sum1 = 0.0f;
        #pragma unroll
        for (int nt = 0; nt < 8; nt++) {
            S[nt][0] = __expf(S[nt][0] - mn0);
            S[nt][1] = __expf(S[nt][1] - mn0);
            S[nt][2] = __expf(S[nt][2] - mn1);
            S[nt][3] = __expf(S[nt][3] - mn1);
            sum0 += S[nt][0] + S[nt][1];
            sum1 += S[nt][2] + S[nt][3];
        }
        sum0 += __shfl_xor_sync(0xffffffffu, sum0, 1);
        sum0 += __shfl_xor_sync(0xffffffffu, sum0, 2);
        sum1 += __shfl_xor_sync(0xffffffffu, sum1, 1);
        sum1 += __shfl_xor_sync(0xffffffffu, sum1, 2);
        s0r = s0r * sc0 + sum0;  s1r = s1r * sc1 + sum1;
        m0r = mn0;  m1r = mn1;

        __syncthreads();             // everyone done with K + mask
        if (it + 1 < 32) { A3_ISSUE_K(it + 1); CP_COMMIT(); CP_WAIT(1); }  // V(it) done
        else             { CP_WAIT(0); }
        __syncthreads();             // V visible

        #pragma unroll
        for (int nt = 0; nt < 16; nt++) {
            O[nt][0] *= sc0; O[nt][1] *= sc0;
            O[nt][2] *= sc1; O[nt][3] *= sc1;
        }

        // O += P(16x64) V(64x128)
        #pragma unroll
        for (int ks = 0; ks < 4; ks++) {
            uint32_t ah[4], al[4];
            split2(S[2*ks][0],   S[2*ks][1],   ah[0], al[0]);
            split2(S[2*ks][2],   S[2*ks][3],   ah[1], al[1]);
            split2(S[2*ks+1][0], S[2*ks+1][1], ah[2], al[2]);
            split2(S[2*ks+1][2], S[2*ks+1][3], ah[3], al[3]);
            const int sv0 = ks * 16;
            #pragma unroll
            for (int nt2 = 0; nt2 < 8; nt2++) {
                const int d0 = nt2 * 16;
                uint32_t voff = (uint32_t)(sv0 + rA) * 256 + (((uint32_t)(d0*2 + cA)) ^ xorv);
                uint32_t bvh[4], bvl[4];
                ldm4t(bvh, sb + A3_VH + voff);
                ldm4t(bvl, sb + A3_VL + voff);
                mma_bf16(O[nt2*2],   ah, bvh);
                mma_bf16(O[nt2*2],   ah, bvl);
                mma_bf16(O[nt2*2],   al, bvh);
                mma_bf16(O[nt2*2+1], ah, bvh + 2);
                mma_bf16(O[nt2*2+1], ah, bvl + 2);
                mma_bf16(O[nt2*2+1], al, bvh + 2);
            }
        }
        __syncthreads();             // V consumed
        if (it + 1 < 32) { A3_ISSUE_V(it + 1); CP_COMMIT(); }
    }

    // normalize + store (row-private)
    const float inv0 = (s0r > 0.0f) ? 1.0f / s0r : 0.0f;
    const float inv1 = (s1r > 0.0f) ? 1.0f / s1r : 0.0f;
    const size_t row0 = (size_t)b*TT + t0 + m0w + (lane >> 2);
    #pragma unroll
    for (int nt = 0; nt < 16; nt++) {
        int col = nt * 8 + c2;
        *(float2*)(out + row0*QD + col)     = make_float2(O[nt][0]*inv0, O[nt][1]*inv0);
        *(float2*)(out + (row0+8)*QD + col) = make_float2(O[nt][2]*inv1, O[nt][3]*inv1);
    }
}

// ---------------- launch ----------------
extern "C" void kernel_launch(void* const* d_in, const int* in_sizes, int n_in,
                              void* d_out, int out_size)
{
    const float* x  = (const float*)d_in[0];
    const void*  mk = d_in[1];
    const float* Wq = (const float*)d_in[2];
    const float* Wk = (const float*)d_in[3];
    const float* Wv = (const float*)d_in[4];
    float* out = (float*)d_out;
    (void)in_sizes; (void)n_in; (void)out_size;

    mask_sniff<<<1, 256>>>((const uint8_t*)mk);
    mask_expand<<<(BB*TT + 255)/256, 256>>>(mk);

    dim3 gp((BB*TT*DD/4 + 255)/256, 4);
    prep_kernel<<<gp, 256>>>(x, Wq, Wk, Wv);

    cudaFuncSetAttribute(proj_kernel, cudaFuncAttributeMaxDynamicSharedMemorySize, PJ_SMEM);
    cudaFuncSetAttribute(attn_kernel, cudaFuncAttributeMaxDynamicSharedMemorySize, A3_SMEM);

    dim3 g1(128, 3);
    proj_kernel<<<g1, 256, PJ_SMEM>>>();
    dim3 g2(TT/64, BB);
    attn_kernel<<<g2, 128, A3_SMEM>>>(out);   // 128 thr = 4 warps, 2 CTAs/SM
}

// round 14
// speedup vs baseline: 1.1983x; 1.1983x over previous
#include <cuda_runtime.h>
#include <cuda_fp16.h>
#include <cstdint>

#define BB 8
#define TT 2048
#define DD 1024
#define QD 128

// ---------------- global scratch (fp16 hi/lo splits) ----------------
__device__ __half g_x_hi[(size_t)BB*TT*DD];
__device__ __half g_x_lo[(size_t)BB*TT*DD];
__device__ __half g_w_hi[3*QD*DD];
__device__ __half g_w_lo[3*QD*DD];
__device__ __half g_q_hi[BB*TT*QD];
__device__ __half g_q_lo[BB*TT*QD];
__device__ __half g_k_hi[BB*TT*QD];
__device__ __half g_k_lo[BB*TT*QD];
__device__ __half g_v_hi[BB*TT*QD];           // row-major [b][t][d]
__device__ __half g_v_lo[BB*TT*QD];
__device__ float g_mask[BB*TT];
__device__ int   g_mask_kind;

// ---------------- helpers ----------------
__device__ __forceinline__ uint32_t smem_u32(const void* p) {
    uint32_t a;
    asm("{ .reg .u64 t; cvta.to.shared.u64 t, %1; cvt.u32.u64 %0, t; }" : "=r"(a) : "l"(p));
    return a;
}
__device__ __forceinline__ uint32_t pk(__half a, __half b) {
    return (uint32_t)__half_as_ushort(a) | ((uint32_t)__half_as_ushort(b) << 16);
}
__device__ __forceinline__ void split2(float a, float b, uint32_t& h, uint32_t& l) {
    __half ha = __float2half_rn(a);
    __half hb = __float2half_rn(b);
    __half la = __float2half_rn(a - __half2float(ha));
    __half lb = __float2half_rn(b - __half2float(hb));
    h = pk(ha, hb); l = pk(la, lb);
}
__device__ __forceinline__ void ldm4(uint32_t r[4], uint32_t a) {
    asm volatile("ldmatrix.sync.aligned.m8n8.x4.shared.b16 {%0,%1,%2,%3}, [%4];"
        : "=r"(r[0]), "=r"(r[1]), "=r"(r[2]), "=r"(r[3]) : "r"(a));
}
__device__ __forceinline__ void ldm4t(uint32_t r[4], uint32_t a) {
    asm volatile("ldmatrix.sync.aligned.m8n8.x4.trans.shared.b16 {%0,%1,%2,%3}, [%4];"
        : "=r"(r[0]), "=r"(r[1]), "=r"(r[2]), "=r"(r[3]) : "r"(a));
}
__device__ __forceinline__ void mma_f16(float* c, const uint32_t* a, const uint32_t* b) {
    asm volatile("mma.sync.aligned.m16n8k16.row.col.f32.f16.f16.f32 "
        "{%0,%1,%2,%3}, {%4,%5,%6,%7}, {%8,%9}, {%0,%1,%2,%3};"
        : "+f"(c[0]), "+f"(c[1]), "+f"(c[2]), "+f"(c[3])
        : "r"(a[0]), "r"(a[1]), "r"(a[2]), "r"(a[3]), "r"(b[0]), "r"(b[1]));
}
__device__ __forceinline__ void cp16(uint32_t dst, const void* src) {
    asm volatile("cp.async.cg.shared.global [%0], [%1], 16;"
        :: "r"(dst), "l"(__cvta_generic_to_global(src)) : "memory");
}
#define CP_COMMIT() asm volatile("cp.async.commit_group;" ::: "memory")
#define CP_WAIT(n)  asm volatile("cp.async.wait_group %0;" :: "n"(n) : "memory")

// ---------------- mask canonicalization (proven) ----------------
__global__ void mask_sniff(const uint8_t* __restrict__ m) {
    __shared__ unsigned r1[256], r3[256];
    unsigned o1 = 0, o3 = 0;
    const uint32_t* w = (const uint32_t*)m;
    for (int i = threadIdx.x; i < (BB*TT)/4; i += 256) {
        uint32_t v = w[i];
        o1 |= (v >> 8) & 0xFFu; o3 |= (v >> 24) & 0xFFu;
    }
    r1[threadIdx.x] = o1; r3[threadIdx.x] = o3;
    __syncthreads();
    for (int s = 128; s; s >>= 1) {
        if (threadIdx.x < s) { r1[threadIdx.x] |= r1[threadIdx.x+s]; r3[threadIdx.x] |= r3[threadIdx.x+s]; }
        __syncthreads();
    }
    if (threadIdx.x == 0) g_mask_kind = r1[0] ? 1 : (r3[0] ? 2 : 0);
}
__global__ void mask_expand(const void* __restrict__ m) {
    int s = blockIdx.x * 256 + threadIdx.x;
    if (s >= BB*TT) return;
    int kind = g_mask_kind;
    float v;
    if (kind == 1)      v = ((const uint8_t*)m)[s] ? 1.0f : 0.0f;
    else if (kind == 2) v = (((const float*)m)[s] != 0.0f) ? 1.0f : 0.0f;
    else                v = ((const int*)m)[s] ? 1.0f : 0.0f;
    g_mask[s] = v;
}

// ---------------- prep: split x and W into fp16 hi/lo ----------------
__global__ __launch_bounds__(256) void prep_kernel(
    const float* __restrict__ x,  const float* __restrict__ Wq,
    const float* __restrict__ Wk, const float* __restrict__ Wv)
{
    const int y = blockIdx.y;
    const size_t i = (size_t)blockIdx.x * 256 + threadIdx.x;
    const float* src; __half *dh, *dl; size_t n4;
    if (y == 0) { src = x; dh = g_x_hi; dl = g_x_lo; n4 = (size_t)BB*TT*DD/4; }
    else {
        src = (y == 1) ? Wq : ((y == 2) ? Wk : Wv);
        dh = g_w_hi + (size_t)(y-1)*QD*DD; dl = g_w_lo + (size_t)(y-1)*QD*DD;
        n4 = (size_t)QD*DD/4;
    }
    if (i >= n4) return;
    float4 v = ((const float4*)src)[i];
    uint32_t h01, l01, h23, l23;
    split2(v.x, v.y, h01, l01);
    split2(v.z, v.w, h23, l23);
    ((uint2*)dh)[i] = make_uint2(h01, h23);
    ((uint2*)dl)[i] = make_uint2(l01, l23);
}

// ---------------- projection GEMM (fp16x3, cp.async 2-stage, 256 thr) ----------------
#define PJ_AH 0
#define PJ_AL 16384
#define PJ_BH 32768
#define PJ_BL 49152
#define PJ_STAGE 65536
#define PJ_SMEM (2*PJ_STAGE + 1024)

__global__ __launch_bounds__(256, 1) void proj_kernel()
{
    extern __shared__ char smraw[];
    char* sp = (char*)(((uintptr_t)smraw + 1023) & ~(uintptr_t)1023);
    uint32_t sb = smem_u32(sp);
    const int tid = threadIdx.x, lane = tid & 31, w = tid >> 5;
    const int m0 = blockIdx.x * 128, z = blockIdx.y;
    const int wm = w & 3, wn = w >> 2;
    const int mrow0 = wm * 32, ncol0 = wn * 64;

    const __half* xh = g_x_hi;
    const __half* xl = g_x_lo;
    const __half* wh = g_w_hi + (size_t)z*QD*DD;
    const __half* wl = g_w_lo + (size_t)z*QD*DD;

    const int mat = lane >> 3;
    const uint32_t xorv = (uint32_t)(lane & 7) << 4;
    const int rA = (mat & 1) * 8 + (lane & 7);
    const int cA = (mat >> 1) * 16;
    const int rB = (mat >> 1) * 8 + (lane & 7);
    const int cB = (mat & 1) * 16;

    const int srow = tid >> 3, sci = tid & 7;
    float C[2][8][4] = {};

    #define PJ_STAGE_CHUNK(c) do {                                              \
        const int _k0 = (c) * 64;                                               \
        uint32_t _bb = sb + (uint32_t)((c) & 1) * PJ_STAGE;                     \
        _Pragma("unroll")                                                       \
        for (int _r = 0; _r < 4; _r++) {                                        \
            int _row = srow + _r * 32;                                          \
            uint32_t _doff = (uint32_t)_row * 128 +                             \
                (((uint32_t)sci * 16) ^ ((uint32_t)(_row & 7) << 4));           \
            const size_t _go = (size_t)(m0 + _row) * DD + _k0 + sci * 8;        \
            const size_t _gw = (size_t)_row * DD + _k0 + sci * 8;               \
            cp16(_bb + PJ_AH + _doff, xh + _go);                                \
            cp16(_bb + PJ_AL + _doff, xl + _go);                                \
            cp16(_bb + PJ_BH + _doff, wh + _gw);                                \
            cp16(_bb + PJ_BL + _doff, wl + _gw);                                \
        } } while (0)

    PJ_STAGE_CHUNK(0); CP_COMMIT();

    for (int c = 0; c < 16; c++) {
        if (c + 1 < 16) { PJ_STAGE_CHUNK(c + 1); CP_COMMIT(); CP_WAIT(1); }
        else            { CP_WAIT(0); }
        __syncthreads();
        const uint32_t bb = sb + (uint32_t)(c & 1) * PJ_STAGE;

        #pragma unroll
        for (int ks = 0; ks < 4; ks++) {
            const int k0 = ks * 16;
            uint32_t ah[2][4], al[2][4];
            #pragma unroll
            for (int mt = 0; mt < 2; mt++) {
                uint32_t aoff = (uint32_t)(mrow0 + mt*16 + rA) * 128 + (((uint32_t)(k0*2 + cA)) ^ xorv);
                ldm4(ah[mt], bb + PJ_AH + aoff);
                ldm4(al[mt], bb + PJ_AL + aoff);
            }
            #pragma unroll
            for (int nt2 = 0; nt2 < 4; nt2++) {
                const int n0 = ncol0 + nt2 * 16;
                uint32_t boff = (uint32_t)(n0 + rB) * 128 + (((uint32_t)(k0*2 + cB)) ^ xorv);
                uint32_t bh[4], bl[4];
                ldm4(bh, bb + PJ_BH + boff);
                ldm4(bl, bb + PJ_BL + boff);
                #pragma unroll
                for (int mt = 0; mt < 2; mt++) {
                    mma_f16(C[mt][nt2*2],   ah[mt], bh);
                    mma_f16(C[mt][nt2*2],   ah[mt], bl);
                    mma_f16(C[mt][nt2*2],   al[mt], bh);
                    mma_f16(C[mt][nt2*2+1], ah[mt], bh + 2);
                    mma_f16(C[mt][nt2*2+1], ah[mt], bl + 2);
                    mma_f16(C[mt][nt2*2+1], al[mt], bh + 2);
                }
            }
        }
        __syncthreads();
    }

    __half *dh, *dl;
    if (z == 0)      { dh = g_q_hi; dl = g_q_lo; }
    else if (z == 1) { dh = g_k_hi; dl = g_k_lo; }
    else             { dh = g_v_hi; dl = g_v_lo; }
    const int r = lane >> 2, c2 = 2 * (lane & 3);
    #pragma unroll
    for (int mt = 0; mt < 2; mt++) {
        #pragma unroll
        for (int nt = 0; nt < 8; nt++) {
            int cc = ncol0 + nt * 8 + c2;
            size_t mg0 = (size_t)(m0 + mrow0 + mt*16 + r);
            uint32_t h, l;
            split2(C[mt][nt][0], C[mt][nt][1], h, l);
            *(uint32_t*)(dh + mg0*QD + cc) = h;
            *(uint32_t*)(dl + mg0*QD + cc) = l;
            split2(C[mt][nt][2], C[mt][nt][3], h, l);
            *(uint32_t*)(dh + (mg0+8)*QD + cc) = h;
            *(uint32_t*)(dl + (mg0+8)*QD + cc) = l;
        }
    }
}

// ---------------- flash attention (fp16, QK 3-term, PV 2-term) ----------------
// grid (16 q-tiles, 8 batches), 256 thr (8 warps x 16 q-rows). Round-10 structure.
#define AT_QH 0
#define AT_QL 32768
#define AT_KH 65536
#define AT_KL 98304
#define AT_VH 131072
#define AT_VL 163840
#define AT_MK 196608
#define AT_SMEM (196608 + 512 + 1024)

__global__ __launch_bounds__(256, 1) void attn_kernel(float* __restrict__ out)
{
    extern __shared__ char smraw[];
    char* sp = (char*)(((uintptr_t)smraw + 1023) & ~(uintptr_t)1023);
    uint32_t sb = smem_u32(sp);
    float* mkS = (float*)(sp + AT_MK);
    const int tid = threadIdx.x, lane = tid & 31, w = tid >> 5;
    const int b = blockIdx.y, t0 = blockIdx.x * 128;
    const int m0w = w * 16;

    const int mat = lane >> 3;
    const uint32_t xorv = (uint32_t)(lane & 7) << 4;
    const int rA = (mat & 1) * 8 + (lane & 7);
    const int cA = (mat >> 1) * 16;
    const int rB = (mat >> 1) * 8 + (lane & 7);
    const int cB = (mat & 1) * 16;

    const int srow = tid >> 4, sci = tid & 15;

    #define AT_ISSUE_K(it) do {                                                 \
        const int _s0 = (it) * 128;                                             \
        _Pragma("unroll")                                                       \
        for (int _r = 0; _r < 8; _r++) {                                        \
            int _row = srow + _r * 16;                                          \
            uint32_t _doff = (uint32_t)_row * 256 +                             \
                (((uint32_t)sci * 16) ^ ((uint32_t)(_row & 7) << 4));           \
            const size_t _g = (size_t)(b*TT + _s0 + _row) * QD + sci * 8;       \
            cp16(sb + AT_KH + _doff, g_k_hi + _g);                              \
            cp16(sb + AT_KL + _doff, g_k_lo + _g);                              \
        }                                                                       \
        if (tid < 32) cp16(sb + AT_MK + tid*16, g_mask + b*TT + _s0 + tid*4);   \
    } while (0)

    #define AT_ISSUE_V(it) do {                                                 \
        const int _s0 = (it) * 128;                                             \
        _Pragma("unroll")                                                       \
        for (int _r = 0; _r < 8; _r++) {                                        \
            int _row = srow + _r * 16;                                          \
            uint32_t _doff = (uint32_t)_row * 256 +                             \
                (((uint32_t)sci * 16) ^ ((uint32_t)(_row & 7) << 4));           \
            const size_t _g = (size_t)(b*TT + _s0 + _row) * QD + sci * 8;       \
            cp16(sb + AT_VH + _doff, g_v_hi + _g);                              \
            cp16(sb + AT_VL + _doff, g_v_lo + _g);                              \
        } } while (0)

    AT_ISSUE_K(0); CP_COMMIT();
    AT_ISSUE_V(0); CP_COMMIT();

    {
        const uint4* qh = (const uint4*)(g_q_hi + (size_t)(b*TT + t0) * QD);
        const uint4* ql = (const uint4*)(g_q_lo + (size_t)(b*TT + t0) * QD);
        #pragma unroll
        for (int r = 0; r < 8; r++) {
            int idx = tid + r * 256;
            int row = idx >> 4;
            uint32_t cb = (uint32_t)(idx & 15) * 16;
            uint32_t doff = (uint32_t)row * 256 + (cb ^ ((uint32_t)(row & 7) << 4));
            *(uint4*)(sp + AT_QH + doff) = qh[idx];
            *(uint4*)(sp + AT_QL + doff) = ql[idx];
        }
    }

    float O[16][4] = {};
    float m0r = -1.0e30f, m1r = -1.0e30f, s0r = 0.0f, s1r = 0.0f;
    const int c2 = 2 * (lane & 3);

    for (int it = 0; it < 16; it++) {
        CP_WAIT(1);
        __syncthreads();

        // S = Q K^T (fp16 3-term)
        float S[16][4] = {};
        #pragma unroll
        for (int ks = 0; ks < 8; ks++) {
            const int k0 = ks * 16;
            uint32_t aqh[4], aql[4];
            uint32_t aoff = (uint32_t)(m0w + rA) * 256 + (((uint32_t)(k0*2 + cA)) ^ xorv);
            ldm4(aqh, sb + AT_QH + aoff);
            ldm4(aql, sb + AT_QL + aoff);
            #pragma unroll
            for (int nt2 = 0; nt2 < 8; nt2++) {
                const int n0 = nt2 * 16;
                uint32_t boff = (uint32_t)(n0 + rB) * 256 + (((uint32_t)(k0*2 + cB)) ^ xorv);
                uint32_t bh[4], bl[4];
                ldm4(bh, sb + AT_KH + boff);
                ldm4(bl, sb + AT_KL + boff);
                mma_f16(S[nt2*2],   aqh, bh);
                mma_f16(S[nt2*2],   aqh, bl);
                mma_f16(S[nt2*2],   aql, bh);
                mma_f16(S[nt2*2+1], aqh, bh + 2);
                mma_f16(S[nt2*2+1], aqh, bl + 2);
                mma_f16(S[nt2*2+1], aql, bh + 2);
            }
        }

        // masked online softmax (rows lane>>2 and +8)
        float mx0 = -3.0e38f, mx1 = -3.0e38f;
        #pragma unroll
        for (int nt = 0; nt < 16; nt++) {
            float k0m = mkS[nt*8 + c2], k1m = mkS[nt*8 + c2 + 1];
            S[nt][0] = (k0m != 0.0f) ? S[nt][0] : -3.0e38f;
            S[nt][1] = (k1m != 0.0f) ? S[nt][1] : -3.0e38f;
            S[nt][2] = (k0m != 0.0f) ? S[nt][2] : -3.0e38f;
            S[nt][3] = (k1m != 0.0f) ? S[nt][3] : -3.0e38f;
            mx0 = fmaxf(mx0, fmaxf(S[nt][0], S[nt][1]));
            mx1 = fmaxf(mx1, fmaxf(S[nt][2], S[nt][3]));
        }
        mx0 = fmaxf(mx0, __shfl_xor_sync(0xffffffffu, mx0, 1));
        mx0 = fmaxf(mx0, __shfl_xor_sync(0xffffffffu, mx0, 2));
        mx1 = fmaxf(mx1, __shfl_xor_sync(0xffffffffu, mx1, 1));
        mx1 = fmaxf(mx1, __shfl_xor_sync(0xffffffffu, mx1, 2));
        float mn0 = fmaxf(m0r, mx0), mn1 = fmaxf(m1r, mx1);
        float sc0 = __expf(m0r - mn0), sc1 = __expf(m1r - mn1);
        float sum0 = 0.0f, sum1 = 0.0f;
        #pragma unroll
        for (int nt = 0; nt < 16; nt++) {
            S[nt][0] = __expf(S[nt][0] - mn0);
            S[nt][1] = __expf(S[nt][1] - mn0);
            S[nt][2] = __expf(S[nt][2] - mn1);
            S[nt][3] = __expf(S[nt][3] - mn1);
            sum0 += S[nt][0] + S[nt][1];
            sum1 += S[nt][2] + S[nt][3];
        }
        sum0 += __shfl_xor_sync(0xffffffffu, sum0, 1);
        sum0 += __shfl_xor_sync(0xffffffffu, sum0, 2);
        sum1 += __shfl_xor_sync(0xffffffffu, sum1, 1);
        sum1 += __shfl_xor_sync(0xffffffffu, sum1, 2);
        s0r = s0r * sc0 + sum0;  s1r = s1r * sc1 + sum1;
        m0r = mn0;  m1r = mn1;

        __syncthreads();
        if (it + 1 < 16) { AT_ISSUE_K(it + 1); CP_COMMIT(); CP_WAIT(1); }
        else             { CP_WAIT(0); }
        __syncthreads();

        #pragma unroll
        for (int nt = 0; nt < 16; nt++) {
            O[nt][0] *= sc0; O[nt][1] *= sc0;
            O[nt][2] *= sc1; O[nt][3] *= sc1;
        }

        // O += P V  (fp16 2-term: Ph*Vh + Ph*Vl; P_lo dropped, err ~2^-12)
        #pragma unroll
        for (int ks = 0; ks < 8; ks++) {
            uint32_t ah[4];
            ah[0] = pk(__float2half_rn(S[2*ks][0]),   __float2half_rn(S[2*ks][1]));
            ah[1] = pk(__float2half_rn(S[2*ks][2]),   __float2half_rn(S[2*ks][3]));
            ah[2] = pk(__float2half_rn(S[2*ks+1][0]), __float2half_rn(S[2*ks+1][1]));
            ah[3] = pk(__float2half_rn(S[2*ks+1][2]), __float2half_rn(S[2*ks+1][3]));
            const int sv0 = ks * 16;
            #pragma unroll
            for (int nt2 = 0; nt2 < 8; nt2++) {
                const int d0 = nt2 * 16;
                uint32_t voff = (uint32_t)(sv0 + rA) * 256 + (((uint32_t)(d0*2 + cA)) ^ xorv);
                uint32_t bvh[4], bvl[4];
                ldm4t(bvh, sb + AT_VH + voff);
                ldm4t(bvl, sb + AT_VL + voff);
                mma_f16(O[nt2*2],   ah, bvh);
                mma_f16(O[nt2*2],   ah, bvl);
                mma_f16(O[nt2*2+1], ah, bvh + 2);
                mma_f16(O[nt2*2+1], ah, bvl + 2);
            }
        }
        __syncthreads();
        if (it + 1 < 16) { AT_ISSUE_V(it + 1); CP_COMMIT(); }
    }

    const float inv0 = (s0r > 0.0f) ? 1.0f / s0r : 0.0f;
    const float inv1 = (s1r > 0.0f) ? 1.0f / s1r : 0.0f;
    const size_t row0 = (size_t)b*TT + t0 + m0w + (lane >> 2);
    #pragma unroll
    for (int nt = 0; nt < 16; nt++) {
        int col = nt * 8 + c2;
        *(float2*)(out + row0*QD + col)     = make_float2(O[nt][0]*inv0, O[nt][1]*inv0);
        *(float2*)(out + (row0+8)*QD + col) = make_float2(O[nt][2]*inv1, O[nt][3]*inv1);
    }
}

// ---------------- launch ----------------
extern "C" void kernel_launch(void* const* d_in, const int* in_sizes, int n_in,
                              void* d_out, int out_size)
{
    const float* x  = (const float*)d_in[0];
    const void*  mk = d_in[1];
    const float* Wq = (const float*)d_in[2];
    const float* Wk = (const float*)d_in[3];
    const float* Wv = (const float*)d_in[4];
    float* out = (float*)d_out;
    (void)in_sizes; (void)n_in; (void)out_size;

    mask_sniff<<<1, 256>>>((const uint8_t*)mk);
    mask_expand<<<(BB*TT + 255)/256, 256>>>(mk);

    dim3 gp((BB*TT*DD/4 + 255)/256, 4);
    prep_kernel<<<gp, 256>>>(x, Wq, Wk, Wv);

    cudaFuncSetAttribute(proj_kernel, cudaFuncAttributeMaxDynamicSharedMemorySize, PJ_SMEM);
    cudaFuncSetAttribute(attn_kernel, cudaFuncAttributeMaxDynamicSharedMemorySize, AT_SMEM);

    dim3 g1(128, 3);
    proj_kernel<<<g1, 256, PJ_SMEM>>>();
    dim3 g2(TT/128, BB);
    attn_kernel<<<g2, 256, AT_SMEM>>>(out);
}

// round 15
// speedup vs baseline: 1.3718x; 1.1449x over previous
#include <cuda_runtime.h>
#include <cuda_fp16.h>
#include <cstdint>

#define BB 8
#define TT 2048
#define DD 1024
#define QD 128

// ---------------- global scratch (fp16 hi/lo splits) ----------------
__device__ __half g_x_hi[(size_t)BB*TT*DD];
__device__ __half g_x_lo[(size_t)BB*TT*DD];
__device__ __half g_w_hi[3*QD*DD];
__device__ __half g_w_lo[3*QD*DD];
__device__ __half g_q_hi[BB*TT*QD];
__device__ __half g_q_lo[BB*TT*QD];
__device__ __half g_k_hi[BB*TT*QD];
__device__ __half g_k_lo[BB*TT*QD];
__device__ __half g_v_hi[BB*TT*QD];
__device__ __half g_v_lo[BB*TT*QD];
// compacted (unmasked) K/V rows, per batch
__device__ __half g_kc_hi[BB*TT*QD];
__device__ __half g_kc_lo[BB*TT*QD];
__device__ __half g_vc_hi[BB*TT*QD];
__device__ __half g_vc_lo[BB*TT*QD];
__device__ int   g_pos[BB*TT];
__device__ int   g_cnt[BB];
__device__ float g_mask[BB*TT];
__device__ int   g_mask_kind;

// ---------------- helpers ----------------
__device__ __forceinline__ uint32_t smem_u32(const void* p) {
    uint32_t a;
    asm("{ .reg .u64 t; cvta.to.shared.u64 t, %1; cvt.u32.u64 %0, t; }" : "=r"(a) : "l"(p));
    return a;
}
__device__ __forceinline__ uint32_t pk(__half a, __half b) {
    return (uint32_t)__half_as_ushort(a) | ((uint32_t)__half_as_ushort(b) << 16);
}
__device__ __forceinline__ void split2(float a, float b, uint32_t& h, uint32_t& l) {
    __half ha = __float2half_rn(a);
    __half hb = __float2half_rn(b);
    __half la = __float2half_rn(a - __half2float(ha));
    __half lb = __float2half_rn(b - __half2float(hb));
    h = pk(ha, hb); l = pk(la, lb);
}
__device__ __forceinline__ void ldm4(uint32_t r[4], uint32_t a) {
    asm volatile("ldmatrix.sync.aligned.m8n8.x4.shared.b16 {%0,%1,%2,%3}, [%4];"
        : "=r"(r[0]), "=r"(r[1]), "=r"(r[2]), "=r"(r[3]) : "r"(a));
}
__device__ __forceinline__ void ldm4t(uint32_t r[4], uint32_t a) {
    asm volatile("ldmatrix.sync.aligned.m8n8.x4.trans.shared.b16 {%0,%1,%2,%3}, [%4];"
        : "=r"(r[0]), "=r"(r[1]), "=r"(r[2]), "=r"(r[3]) : "r"(a));
}
__device__ __forceinline__ void mma_f16(float* c, const uint32_t* a, const uint32_t* b) {
    asm volatile("mma.sync.aligned.m16n8k16.row.col.f32.f16.f16.f32 "
        "{%0,%1,%2,%3}, {%4,%5,%6,%7}, {%8,%9}, {%0,%1,%2,%3};"
        : "+f"(c[0]), "+f"(c[1]), "+f"(c[2]), "+f"(c[3])
        : "r"(a[0]), "r"(a[1]), "r"(a[2]), "r"(a[3]), "r"(b[0]), "r"(b[1]));
}
__device__ __forceinline__ void cp16(uint32_t dst, const void* src) {
    asm volatile("cp.async.cg.shared.global [%0], [%1], 16;"
        :: "r"(dst), "l"(__cvta_generic_to_global(src)) : "memory");
}
#define CP_COMMIT() asm volatile("cp.async.commit_group;" ::: "memory")
#define CP_WAIT(n)  asm volatile("cp.async.wait_group %0;" :: "n"(n) : "memory")

// ---------------- mask canonicalization (proven) ----------------
__global__ void mask_sniff(const uint8_t* __restrict__ m) {
    __shared__ unsigned r1[256], r3[256];
    unsigned o1 = 0, o3 = 0;
    const uint32_t* w = (const uint32_t*)m;
    for (int i = threadIdx.x; i < (BB*TT)/4; i += 256) {
        uint32_t v = w[i];
        o1 |= (v >> 8) & 0xFFu; o3 |= (v >> 24) & 0xFFu;
    }
    r1[threadIdx.x] = o1; r3[threadIdx.x] = o3;
    __syncthreads();
    for (int s = 128; s; s >>= 1) {
        if (threadIdx.x < s) { r1[threadIdx.x] |= r1[threadIdx.x+s]; r3[threadIdx.x] |= r3[threadIdx.x+s]; }
        __syncthreads();
    }
    if (threadIdx.x == 0) g_mask_kind = r1[0] ? 1 : (r3[0] ? 2 : 0);
}
__global__ void mask_expand(const void* __restrict__ m) {
    int s = blockIdx.x * 256 + threadIdx.x;
    if (s >= BB*TT) return;
    int kind = g_mask_kind;
    float v;
    if (kind == 1)      v = ((const uint8_t*)m)[s] ? 1.0f : 0.0f;
    else if (kind == 2) v = (((const float*)m)[s] != 0.0f) ? 1.0f : 0.0f;
    else                v = ((const int*)m)[s] ? 1.0f : 0.0f;
    g_mask[s] = v;
}

// ---------------- per-batch mask prefix scan ----------------
__global__ __launch_bounds__(1024) void scan_kernel() {
    __shared__ int sc[1024];
    const int b = blockIdx.x, tid = threadIdx.x;
    int a0 = (g_mask[b*TT + 2*tid]     != 0.0f) ? 1 : 0;
    int a1 = (g_mask[b*TT + 2*tid + 1] != 0.0f) ? 1 : 0;
    int part = a0 + a1;
    sc[tid] = part;
    __syncthreads();
    for (int off = 1; off < 1024; off <<= 1) {
        int v = (tid >= off) ? sc[tid - off] : 0;
        __syncthreads();
        sc[tid] += v;
        __syncthreads();
    }
    int excl = sc[tid] - part;
    g_pos[b*TT + 2*tid]     = excl;
    g_pos[b*TT + 2*tid + 1] = excl + a0;
    if (tid == 1023) g_cnt[b] = sc[tid];
}

// ---------------- zero-fill tail of compacted arrays (NaN safety) ----------------
__global__ __launch_bounds__(256) void zerotail_kernel() {
    const int b = blockIdx.x;
    const int cnt = g_cnt[b];
    const int end = (cnt + 127) & ~127;
    const uint4 z = make_uint4(0, 0, 0, 0);
    for (int i = threadIdx.x; i < (end - cnt) * 16; i += 256) {
        int r = cnt + (i >> 4), ch = i & 15;
        size_t base = (size_t)(b*TT + r) * QD;
        *((uint4*)(g_kc_hi + base) + ch) = z;
        *((uint4*)(g_kc_lo + base) + ch) = z;
        *((uint4*)(g_vc_hi + base) + ch) = z;
        *((uint4*)(g_vc_lo + base) + ch) = z;
    }
}

// ---------------- gather unmasked K/V rows ----------------
// grid (TT/4, BB), 256 thr: 4 rows/CTA, 64 threads per row (4 arrays x 16 uint4).
__global__ __launch_bounds__(256) void gather_kernel() {
    const int b = blockIdx.y;
    const int row = blockIdx.x * 4 + (threadIdx.x >> 6);
    const int c = threadIdx.x & 63;
    if (g_mask[b*TT + row] == 0.0f) return;
    const int dst = g_pos[b*TT + row];
    const int a = c >> 4, ch = c & 15;
    const __half* src = (a == 0) ? g_k_hi : (a == 1) ? g_k_lo : (a == 2) ? g_v_hi : g_v_lo;
    __half*       dp  = (a == 0) ? g_kc_hi : (a == 1) ? g_kc_lo : (a == 2) ? g_vc_hi : g_vc_lo;
    *((uint4*)(dp + (size_t)(b*TT + dst)*QD) + ch) =
        *((const uint4*)(src + (size_t)(b*TT + row)*QD) + ch);
}

// ---------------- prep: split x and W into fp16 hi/lo ----------------
__global__ __launch_bounds__(256) void prep_kernel(
    const float* __restrict__ x,  const float* __restrict__ Wq,
    const float* __restrict__ Wk, const float* __restrict__ Wv)
{
    const int y = blockIdx.y;
    const size_t i = (size_t)blockIdx.x * 256 + threadIdx.x;
    const float* src; __half *dh, *dl; size_t n4;
    if (y == 0) { src = x; dh = g_x_hi; dl = g_x_lo; n4 = (size_t)BB*TT*DD/4; }
    else {
        src = (y == 1) ? Wq : ((y == 2) ? Wk : Wv);
        dh = g_w_hi + (size_t)(y-1)*QD*DD; dl = g_w_lo + (size_t)(y-1)*QD*DD;
        n4 = (size_t)QD*DD/4;
    }
    if (i >= n4) return;
    float4 v = ((const float4*)src)[i];
    uint32_t h01, l01, h23, l23;
    split2(v.x, v.y, h01, l01);
    split2(v.z, v.w, h23, l23);
    ((uint2*)dh)[i] = make_uint2(h01, h23);
    ((uint2*)dl)[i] = make_uint2(l01, l23);
}

// ---------------- projection GEMM (fp16x3, cp.async 2-stage, 256 thr) ----------------
#define PJ_AH 0
#define PJ_AL 16384
#define PJ_BH 32768
#define PJ_BL 49152
#define PJ_STAGE 65536
#define PJ_SMEM (2*PJ_STAGE + 1024)

__global__ __launch_bounds__(256, 1) void proj_kernel()
{
    extern __shared__ char smraw[];
    char* sp = (char*)(((uintptr_t)smraw + 1023) & ~(uintptr_t)1023);
    uint32_t sb = smem_u32(sp);
    const int tid = threadIdx.x, lane = tid & 31, w = tid >> 5;
    const int m0 = blockIdx.x * 128, z = blockIdx.y;
    const int wm = w & 3, wn = w >> 2;
    const int mrow0 = wm * 32, ncol0 = wn * 64;

    const __half* xh = g_x_hi;
    const __half* xl = g_x_lo;
    const __half* wh = g_w_hi + (size_t)z*QD*DD;
    const __half* wl = g_w_lo + (size_t)z*QD*DD;

    const int mat = lane >> 3;
    const uint32_t xorv = (uint32_t)(lane & 7) << 4;
    const int rA = (mat & 1) * 8 + (lane & 7);
    const int cA = (mat >> 1) * 16;
    const int rB = (mat >> 1) * 8 + (lane & 7);
    const int cB = (mat & 1) * 16;

    const int srow = tid >> 3, sci = tid & 7;
    float C[2][8][4] = {};

    #define PJ_STAGE_CHUNK(c) do {                                              \
        const int _k0 = (c) * 64;                                               \
        uint32_t _bb = sb + (uint32_t)((c) & 1) * PJ_STAGE;                     \
        _Pragma("unroll")                                                       \
        for (int _r = 0; _r < 4; _r++) {                                        \
            int _row = srow + _r * 32;                                          \
            uint32_t _doff = (uint32_t)_row * 128 +                             \
                (((uint32_t)sci * 16) ^ ((uint32_t)(_row & 7) << 4));           \
            const size_t _go = (size_t)(m0 + _row) * DD + _k0 + sci * 8;        \
            const size_t _gw = (size_t)_row * DD + _k0 + sci * 8;               \
            cp16(_bb + PJ_AH + _doff, xh + _go);                                \
            cp16(_bb + PJ_AL + _doff, xl + _go);                                \
            cp16(_bb + PJ_BH + _doff, wh + _gw);                                \
            cp16(_bb + PJ_BL + _doff, wl + _gw);                                \
        } } while (0)

    PJ_STAGE_CHUNK(0); CP_COMMIT();

    for (int c = 0; c < 16; c++) {
        if (c + 1 < 16) { PJ_STAGE_CHUNK(c + 1); CP_COMMIT(); CP_WAIT(1); }
        else            { CP_WAIT(0); }
        __syncthreads();
        const uint32_t bb = sb + (uint32_t)(c & 1) * PJ_STAGE;

        #pragma unroll
        for (int ks = 0; ks < 4; ks++) {
            const int k0 = ks * 16;
            uint32_t ah[2][4], al[2][4];
            #pragma unroll
            for (int mt = 0; mt < 2; mt++) {
                uint32_t aoff = (uint32_t)(mrow0 + mt*16 + rA) * 128 + (((uint32_t)(k0*2 + cA)) ^ xorv);
                ldm4(ah[mt], bb + PJ_AH + aoff);
                ldm4(al[mt], bb + PJ_AL + aoff);
            }
            #pragma unroll
            for (int nt2 = 0; nt2 < 4; nt2++) {
                const int n0 = ncol0 + nt2 * 16;
                uint32_t boff = (uint32_t)(n0 + rB) * 128 + (((uint32_t)(k0*2 + cB)) ^ xorv);
                uint32_t bh[4], bl[4];
                ldm4(bh, bb + PJ_BH + boff);
                ldm4(bl, bb + PJ_BL + boff);
                #pragma unroll
                for (int mt = 0; mt < 2; mt++) {
                    mma_f16(C[mt][nt2*2],   ah[mt], bh);
                    mma_f16(C[mt][nt2*2],   ah[mt], bl);
                    mma_f16(C[mt][nt2*2],   al[mt], bh);
                    mma_f16(C[mt][nt2*2+1], ah[mt], bh + 2);
                    mma_f16(C[mt][nt2*2+1], ah[mt], bl + 2);
                    mma_f16(C[mt][nt2*2+1], al[mt], bh + 2);
                }
            }
        }
        __syncthreads();
    }

    __half *dh, *dl;
    if (z == 0)      { dh = g_q_hi; dl = g_q_lo; }
    else if (z == 1) { dh = g_k_hi; dl = g_k_lo; }
    else             { dh = g_v_hi; dl = g_v_lo; }
    const int r = lane >> 2, c2 = 2 * (lane & 3);
    #pragma unroll
    for (int mt = 0; mt < 2; mt++) {
        #pragma unroll
        for (int nt = 0; nt < 8; nt++) {
            int cc = ncol0 + nt * 8 + c2;
            size_t mg0 = (size_t)(m0 + mrow0 + mt*16 + r);
            uint32_t h, l;
            split2(C[mt][nt][0], C[mt][nt][1], h, l);
            *(uint32_t*)(dh + mg0*QD + cc) = h;
            *(uint32_t*)(dl + mg0*QD + cc) = l;
            split2(C[mt][nt][2], C[mt][nt][3], h, l);
            *(uint32_t*)(dh + (mg0+8)*QD + cc) = h;
            *(uint32_t*)(dl + (mg0+8)*QD + cc) = l;
        }
    }
}

// ---------------- flash attention over COMPACTED keys ----------------
// grid (16 q-tiles, 8 batches), 256 thr. Tiles = ceil(cnt/128); validity by index.
#define AT_QH 0
#define AT_QL 32768
#define AT_KH 65536
#define AT_KL 98304
#define AT_VH 131072
#define AT_VL 163840
#define AT_SMEM (196608 + 1024)

__global__ __launch_bounds__(256, 1) void attn_kernel(float* __restrict__ out)
{
    extern __shared__ char smraw[];
    char* sp = (char*)(((uintptr_t)smraw + 1023) & ~(uintptr_t)1023);
    uint32_t sb = smem_u32(sp);
    const int tid = threadIdx.x, lane = tid & 31, w = tid >> 5;
    const int b = blockIdx.y, t0 = blockIdx.x * 128;
    const int m0w = w * 16;

    const int mat = lane >> 3;
    const uint32_t xorv = (uint32_t)(lane & 7) << 4;
    const int rA = (mat & 1) * 8 + (lane & 7);
    const int cA = (mat >> 1) * 16;
    const int rB = (mat >> 1) * 8 + (lane & 7);
    const int cB = (mat & 1) * 16;

    const int srow = tid >> 4, sci = tid & 15;
    const int cnt = g_cnt[b];
    const int ntiles = (cnt + 127) >> 7;

    #define AT_ISSUE_K(it) do {                                                 \
        const int _s0 = (it) * 128;                                             \
        _Pragma("unroll")                                                       \
        for (int _r = 0; _r < 8; _r++) {                                        \
            int _row = srow + _r * 16;                                          \
            uint32_t _doff = (uint32_t)_row * 256 +                             \
                (((uint32_t)sci * 16) ^ ((uint32_t)(_row & 7) << 4));           \
            const size_t _g = (size_t)(b*TT + _s0 + _row) * QD + sci * 8;       \
            cp16(sb + AT_KH + _doff, g_kc_hi + _g);                             \
            cp16(sb + AT_KL + _doff, g_kc_lo + _g);                             \
        } } while (0)

    #define AT_ISSUE_V(it) do {                                                 \
        const int _s0 = (it) * 128;                                             \
        _Pragma("unroll")                                                       \
        for (int _r = 0; _r < 8; _r++) {                                        \
            int _row = srow + _r * 16;                                          \
            uint32_t _doff = (uint32_t)_row * 256 +                             \
                (((uint32_t)sci * 16) ^ ((uint32_t)(_row & 7) << 4));           \
            const size_t _g = (size_t)(b*TT + _s0 + _row) * QD + sci * 8;       \
            cp16(sb + AT_VH + _doff, g_vc_hi + _g);                             \
            cp16(sb + AT_VL + _doff, g_vc_lo + _g);                             \
        } } while (0)

    float O[16][4] = {};
    float m0r = -1.0e30f, m1r = -1.0e30f, s0r = 0.0f, s1r = 0.0f;
    const int c2 = 2 * (lane & 3);

    if (ntiles > 0) {
        AT_ISSUE_K(0); CP_COMMIT();
        AT_ISSUE_V(0); CP_COMMIT();

        const uint4* qh = (const uint4*)(g_q_hi + (size_t)(b*TT + t0) * QD);
        const uint4* ql = (const uint4*)(g_q_lo + (size_t)(b*TT + t0) * QD);
        #pragma unroll
        for (int r = 0; r < 8; r++) {
            int idx = tid + r * 256;
            int row = idx >> 4;
            uint32_t cb = (uint32_t)(idx & 15) * 16;
            uint32_t doff = (uint32_t)row * 256 + (cb ^ ((uint32_t)(row & 7) << 4));
            *(uint4*)(sp + AT_QH + doff) = qh[idx];
            *(uint4*)(sp + AT_QL + doff) = ql[idx];
        }

        for (int it = 0; it < ntiles; it++) {
            CP_WAIT(1);
            __syncthreads();

            // S = Q K^T (fp16 3-term)
            float S[16][4] = {};
            #pragma unroll
            for (int ks = 0; ks < 8; ks++) {
                const int k0 = ks * 16;
                uint32_t aqh[4], aql[4];
                uint32_t aoff = (uint32_t)(m0w + rA) * 256 + (((uint32_t)(k0*2 + cA)) ^ xorv);
                ldm4(aqh, sb + AT_QH + aoff);
                ldm4(aql, sb + AT_QL + aoff);
                #pragma unroll
                for (int nt2 = 0; nt2 < 8; nt2++) {
                    const int n0 = nt2 * 16;
                    uint32_t boff = (uint32_t)(n0 + rB) * 256 + (((uint32_t)(k0*2 + cB)) ^ xorv);
                    uint32_t bh[4], bl[4];
                    ldm4(bh, sb + AT_KH + boff);
                    ldm4(bl, sb + AT_KL + boff);
                    mma_f16(S[nt2*2],   aqh, bh);
                    mma_f16(S[nt2*2],   aqh, bl);
                    mma_f16(S[nt2*2],   aql, bh);
                    mma_f16(S[nt2*2+1], aqh, bh + 2);
                    mma_f16(S[nt2*2+1], aqh, bl + 2);
                    mma_f16(S[nt2*2+1], aql, bh + 2);
                }
            }

            // online softmax; validity = compacted index < cnt
            const int base = it * 128;
            float mx0 = -3.0e38f, mx1 = -3.0e38f;
            #pragma unroll
            for (int nt = 0; nt < 16; nt++) {
                bool v0 = (base + nt*8 + c2)     < cnt;
                bool v1 = (base + nt*8 + c2 + 1) < cnt;
                S[nt][0] = v0 ? S[nt][0] : -3.0e38f;
                S[nt][1] = v1 ? S[nt][1] : -3.0e38f;
                S[nt][2] = v0 ? S[nt][2] : -3.0e38f;
                S[nt][3] = v1 ? S[nt][3] : -3.0e38f;
                mx0 = fmaxf(mx0, fmaxf(S[nt][0], S[nt][1]));
                mx1 = fmaxf(mx1, fmaxf(S[nt][2], S[nt][3]));
            }
            mx0 = fmaxf(mx0, __shfl_xor_sync(0xffffffffu, mx0, 1));
            mx0 = fmaxf(mx0, __shfl_xor_sync(0xffffffffu, mx0, 2));
            mx1 = fmaxf(mx1, __shfl_xor_sync(0xffffffffu, mx1, 1));
            mx1 = fmaxf(mx1, __shfl_xor_sync(0xffffffffu, mx1, 2));
            float mn0 = fmaxf(m0r, mx0), mn1 = fmaxf(m1r, mx1);
            float sc0 = __expf(m0r - mn0), sc1 = __expf(m1r - mn1);
            float sum0 = 0.0f, sum1 = 0.0f;
            #pragma unroll
            for (int nt = 0; nt < 16; nt++) {
                S[nt][0] = __expf(S[nt][0] - mn0);
                S[nt][1] = __expf(S[nt][1] - mn0);
                S[nt][2] = __expf(S[nt][2] - mn1);
                S[nt][3] = __expf(S[nt][3] - mn1);
                sum0 += S[nt][0] + S[nt][1];
                sum1 += S[nt][2] + S[nt][3];
            }
            sum0 += __shfl_xor_sync(0xffffffffu, sum0, 1);
            sum0 += __shfl_xor_sync(0xffffffffu, sum0, 2);
            sum1 += __shfl_xor_sync(0xffffffffu, sum1, 1);
            sum1 += __shfl_xor_sync(0xffffffffu, sum1, 2);
            s0r = s0r * sc0 + sum0;  s1r = s1r * sc1 + sum1;
            m0r = mn0;  m1r = mn1;

            __syncthreads();
            if (it + 1 < ntiles) { AT_ISSUE_K(it + 1); CP_COMMIT(); CP_WAIT(1); }
            else                 { CP_WAIT(0); }
            __syncthreads();

            #pragma unroll
            for (int nt = 0; nt < 16; nt++) {
                O[nt][0] *= sc0; O[nt][1] *= sc0;
                O[nt][2] *= sc1; O[nt][3] *= sc1;
            }

            // O += P V  (fp16 2-term)
            #pragma unroll
            for (int ks = 0; ks < 8; ks++) {
                uint32_t ah[4];
                ah[0] = pk(__float2half_rn(S[2*ks][0]),   __float2half_rn(S[2*ks][1]));
                ah[1] = pk(__float2half_rn(S[2*ks][2]),   __float2half_rn(S[2*ks][3]));
                ah[2] = pk(__float2half_rn(S[2*ks+1][0]), __float2half_rn(S[2*ks+1][1]));
                ah[3] = pk(__float2half_rn(S[2*ks+1][2]), __float2half_rn(S[2*ks+1][3]));
                const int sv0 = ks * 16;
                #pragma unroll
                for (int nt2 = 0; nt2 < 8; nt2++) {
                    const int d0 = nt2 * 16;
                    uint32_t voff = (uint32_t)(sv0 + rA) * 256 + (((uint32_t)(d0*2 + cA)) ^ xorv);
                    uint32_t bvh[4], bvl[4];
                    ldm4t(bvh, sb + AT_VH + voff);
                    ldm4t(bvl, sb + AT_VL + voff);
                    mma_f16(O[nt2*2],   ah, bvh);
                    mma_f16(O[nt2*2],   ah, bvl);
                    mma_f16(O[nt2*2+1], ah, bvh + 2);
                    mma_f16(O[nt2*2+1], ah, bvl + 2);
                }
            }
            __syncthreads();
            if (it + 1 < ntiles) { AT_ISSUE_V(it + 1); CP_COMMIT(); }
        }
    }

    const float inv0 = (s0r > 0.0f) ? 1.0f / s0r : 0.0f;
    const float inv1 = (s1r > 0.0f) ? 1.0f / s1r : 0.0f;
    const size_t row0 = (size_t)b*TT + t0 + m0w + (lane >> 2);
    #pragma unroll
    for (int nt = 0; nt < 16; nt++) {
        int col = nt * 8 + c2;
        *(float2*)(out + row0*QD + col)     = make_float2(O[nt][0]*inv0, O[nt][1]*inv0);
        *(float2*)(out + (row0+8)*QD + col) = make_float2(O[nt][2]*inv1, O[nt][3]*inv1);
    }
}

// ---------------- launch ----------------
extern "C" void kernel_launch(void* const* d_in, const int* in_sizes, int n_in,
                              void* d_out, int out_size)
{
    const float* x  = (const float*)d_in[0];
    const void*  mk = d_in[1];
    const float* Wq = (const float*)d_in[2];
    const float* Wk = (const float*)d_in[3];
    const float* Wv = (const float*)d_in[4];
    float* out = (float*)d_out;
    (void)in_sizes; (void)n_in; (void)out_size;

    mask_sniff<<<1, 256>>>((const uint8_t*)mk);
    mask_expand<<<(BB*TT + 255)/256, 256>>>(mk);
    scan_kernel<<<BB, 1024>>>();

    dim3 gp((BB*TT*DD/4 + 255)/256, 4);
    prep_kernel<<<gp, 256>>>(x, Wq, Wk, Wv);

    cudaFuncSetAttribute(proj_kernel, cudaFuncAttributeMaxDynamicSharedMemorySize, PJ_SMEM);
    cudaFuncSetAttribute(attn_kernel, cudaFuncAttributeMaxDynamicSharedMemorySize, AT_SMEM);

    dim3 g1(128, 3);
    proj_kernel<<<g1, 256, PJ_SMEM>>>();

    zerotail_kernel<<<BB, 256>>>();
    dim3 gg(TT/4, BB);
    gather_kernel<<<gg, 256>>>();

    dim3 g2(TT/128, BB);
    attn_kernel<<<g2, 256, AT_SMEM>>>(out);
}

// round 16
// speedup vs baseline: 1.5673x; 1.1425x over previous
#include <cuda_runtime.h>
#include <cuda_fp16.h>
#include <cstdint>

#define BB 8
#define TT 2048
#define DD 1024
#define QD 128

// ---------------- global scratch (fp16 hi/lo splits) ----------------
__device__ __half g_x_hi[(size_t)BB*TT*DD];
__device__ __half g_x_lo[(size_t)BB*TT*DD];
__device__ __half g_w_hi[3*QD*DD];
__device__ __half g_w_lo[3*QD*DD];
__device__ __half g_q_hi[BB*TT*QD];
__device__ __half g_q_lo[BB*TT*QD];
__device__ __half g_k_hi[BB*TT*QD];
__device__ __half g_k_lo[BB*TT*QD];
__device__ __half g_v_hi[BB*TT*QD];
__device__ __half g_v_lo[BB*TT*QD];
// compacted (unmasked) K/V rows, per batch
__device__ __half g_kc_hi[BB*TT*QD];
__device__ __half g_kc_lo[BB*TT*QD];
__device__ __half g_vc_hi[BB*TT*QD];
__device__ __half g_vc_lo[BB*TT*QD];
__device__ int   g_pos[BB*TT];
__device__ int   g_cnt[BB];
__device__ float g_mask[BB*TT];

// ---------------- helpers ----------------
__device__ __forceinline__ uint32_t smem_u32(const void* p) {
    uint32_t a;
    asm("{ .reg .u64 t; cvta.to.shared.u64 t, %1; cvt.u32.u64 %0, t; }" : "=r"(a) : "l"(p));
    return a;
}
__device__ __forceinline__ uint32_t pk(__half a, __half b) {
    return (uint32_t)__half_as_ushort(a) | ((uint32_t)__half_as_ushort(b) << 16);
}
__device__ __forceinline__ void split2(float a, float b, uint32_t& h, uint32_t& l) {
    __half ha = __float2half_rn(a);
    __half hb = __float2half_rn(b);
    __half la = __float2half_rn(a - __half2float(ha));
    __half lb = __float2half_rn(b - __half2float(hb));
    h = pk(ha, hb); l = pk(la, lb);
}
__device__ __forceinline__ void ldm4(uint32_t r[4], uint32_t a) {
    asm volatile("ldmatrix.sync.aligned.m8n8.x4.shared.b16 {%0,%1,%2,%3}, [%4];"
        : "=r"(r[0]), "=r"(r[1]), "=r"(r[2]), "=r"(r[3]) : "r"(a));
}
__device__ __forceinline__ void ldm4t(uint32_t r[4], uint32_t a) {
    asm volatile("ldmatrix.sync.aligned.m8n8.x4.trans.shared.b16 {%0,%1,%2,%3}, [%4];"
        : "=r"(r[0]), "=r"(r[1]), "=r"(r[2]), "=r"(r[3]) : "r"(a));
}
__device__ __forceinline__ void mma_f16(float* c, const uint32_t* a, const uint32_t* b) {
    asm volatile("mma.sync.aligned.m16n8k16.row.col.f32.f16.f16.f32 "
        "{%0,%1,%2,%3}, {%4,%5,%6,%7}, {%8,%9}, {%0,%1,%2,%3};"
        : "+f"(c[0]), "+f"(c[1]), "+f"(c[2]), "+f"(c[3])
        : "r"(a[0]), "r"(a[1]), "r"(a[2]), "r"(a[3]), "r"(b[0]), "r"(b[1]));
}
__device__ __forceinline__ void cp16(uint32_t dst, const void* src) {
    asm volatile("cp.async.cg.shared.global [%0], [%1], 16;"
        :: "r"(dst), "l"(__cvta_generic_to_global(src)) : "memory");
}
#define CP_COMMIT() asm volatile("cp.async.commit_group;" ::: "memory")
#define CP_WAIT(n)  asm volatile("cp.async.wait_group %0;" :: "n"(n) : "memory")

// ---------------- fused mask pipeline: sniff + expand + scan + zerotail ----------------
// 8 blocks (one per batch) x 1024 threads. Per-batch dtype sniff is safe:
// 512 words of random 0/1 data -> P(misdetect) ~ 2^-512.
__global__ __launch_bounds__(1024) void mask_scan_kernel(const uint8_t* __restrict__ m)
{
    __shared__ int sc[1024];
    __shared__ unsigned red[64];
    const int b = blockIdx.x, tid = threadIdx.x;

    // sniff this batch's guaranteed-present 2048-byte window
    unsigned o1 = 0, o3 = 0;
    if (tid < 512) {
        uint32_t v = ((const uint32_t*)m)[b*512 + tid];
        o1 = (v >> 8) & 0xFFu; o3 = (v >> 24) & 0xFFu;
    }
    #pragma unroll
    for (int off = 16; off; off >>= 1) {
        o1 |= __shfl_xor_sync(0xffffffffu, o1, off);
        o3 |= __shfl_xor_sync(0xffffffffu, o3, off);
    }
    if ((tid & 31) == 0) { red[(tid>>5)*2] = o1; red[(tid>>5)*2 + 1] = o3; }
    __syncthreads();
    if (tid == 0) {
        unsigned a1 = 0, a3 = 0;
        for (int i = 0; i < 32; i++) { a1 |= red[i*2]; a3 |= red[i*2+1]; }
        red[0] = a1 ? 1u : (a3 ? 2u : 0u);   // 1=uint8, 2=f32, 0=int32
    }
    __syncthreads();
    const int kind = (int)red[0];

    // expand 2 elements per thread
    const int s0 = b*TT + 2*tid;
    int e0, e1;
    if (kind == 1)      { e0 = m[s0] != 0;                      e1 = m[s0+1] != 0; }
    else if (kind == 2) { e0 = ((const float*)m)[s0] != 0.0f;   e1 = ((const float*)m)[s0+1] != 0.0f; }
    else                { e0 = ((const int*)m)[s0] != 0;        e1 = ((const int*)m)[s0+1] != 0; }
    g_mask[s0]     = e0 ? 1.0f : 0.0f;
    g_mask[s0 + 1] = e1 ? 1.0f : 0.0f;

    // inclusive scan over 2048 elements (2 per thread)
    int part = e0 + e1;
    sc[tid] = part;
    __syncthreads();
    for (int off = 1; off < 1024; off <<= 1) {
        int v = (tid >= off) ? sc[tid - off] : 0;
        __syncthreads();
        sc[tid] += v;
        __syncthreads();
    }
    int excl = sc[tid] - part;
    g_pos[s0]     = excl;
    g_pos[s0 + 1] = excl + e0;
    const int cnt = sc[1023];
    if (tid == 1023) g_cnt[b] = cnt;

    // zero-fill compacted tail rows (NaN safety for padded MMA tiles)
    const int end = (cnt + 127) & ~127;
    const uint4 z = make_uint4(0, 0, 0, 0);
    for (int i = tid; i < (end - cnt) * 16; i += 1024) {
        int r = cnt + (i >> 4), ch = i & 15;
        size_t base = (size_t)(b*TT + r) * QD;
        *((uint4*)(g_kc_hi + base) + ch) = z;
        *((uint4*)(g_kc_lo + base) + ch) = z;
        *((uint4*)(g_vc_hi + base) + ch) = z;
        *((uint4*)(g_vc_lo + base) + ch) = z;
    }
}

// ---------------- gather unmasked K/V rows ----------------
__global__ __launch_bounds__(256) void gather_kernel() {
    const int b = blockIdx.y;
    const int row = blockIdx.x * 4 + (threadIdx.x >> 6);
    const int c = threadIdx.x & 63;
    if (g_mask[b*TT + row] == 0.0f) return;
    const int dst = g_pos[b*TT + row];
    const int a = c >> 4, ch = c & 15;
    const __half* src = (a == 0) ? g_k_hi : (a == 1) ? g_k_lo : (a == 2) ? g_v_hi : g_v_lo;
    __half*       dp  = (a == 0) ? g_kc_hi : (a == 1) ? g_kc_lo : (a == 2) ? g_vc_hi : g_vc_lo;
    *((uint4*)(dp + (size_t)(b*TT + dst)*QD) + ch) =
        *((const uint4*)(src + (size_t)(b*TT + row)*QD) + ch);
}

// ---------------- prep: split x / W into fp16 hi/lo (wide, exact grids) ----------------
__global__ __launch_bounds__(256) void prep_x_kernel(const float* __restrict__ x) {
    const size_t i = (size_t)blockIdx.x * 256 + threadIdx.x;   // 8-float group
    const float4* s = (const float4*)x;
    float4 a = s[2*i], c = s[2*i + 1];
    uint32_t h0,l0,h1,l1,h2,l2,h3,l3;
    split2(a.x, a.y, h0, l0); split2(a.z, a.w, h1, l1);
    split2(c.x, c.y, h2, l2); split2(c.z, c.w, h3, l3);
    ((uint4*)g_x_hi)[i] = make_uint4(h0, h1, h2, h3);
    ((uint4*)g_x_lo)[i] = make_uint4(l0, l1, l2, l3);
}
__global__ __launch_bounds__(256) void prep_w_kernel(
    const float* __restrict__ Wq, const float* __restrict__ Wk,
    const float* __restrict__ Wv)
{
    const int z = blockIdx.y;
    const float* W = (z == 0) ? Wq : (z == 1) ? Wk : Wv;
    const size_t i = (size_t)blockIdx.x * 256 + threadIdx.x;   // 8-float group
    const float4* s = (const float4*)W;
    float4 a = s[2*i], c = s[2*i + 1];
    uint32_t h0,l0,h1,l1,h2,l2,h3,l3;
    split2(a.x, a.y, h0, l0); split2(a.z, a.w, h1, l1);
    split2(c.x, c.y, h2, l2); split2(c.z, c.w, h3, l3);
    const size_t off = (size_t)z * QD * DD / 8;
    ((uint4*)g_w_hi)[off + i] = make_uint4(h0, h1, h2, h3);
    ((uint4*)g_w_lo)[off + i] = make_uint4(l0, l1, l2, l3);
}

// ---------------- projection GEMM (fp16x3, cp.async 2-stage, 256 thr) ----------------
#define PJ_AH 0
#define PJ_AL 16384
#define PJ_BH 32768
#define PJ_BL 49152
#define PJ_STAGE 65536
#define PJ_SMEM (2*PJ_STAGE + 1024)

__global__ __launch_bounds__(256, 1) void proj_kernel()
{
    extern __shared__ char smraw[];
    char* sp = (char*)(((uintptr_t)smraw + 1023) & ~(uintptr_t)1023);
    uint32_t sb = smem_u32(sp);
    const int tid = threadIdx.x, lane = tid & 31, w = tid >> 5;
    const int m0 = blockIdx.x * 128, z = blockIdx.y;
    const int wm = w & 3, wn = w >> 2;
    const int mrow0 = wm * 32, ncol0 = wn * 64;

    const __half* xh = g_x_hi;
    const __half* xl = g_x_lo;
    const __half* wh = g_w_hi + (size_t)z*QD*DD;
    const __half* wl = g_w_lo + (size_t)z*QD*DD;

    const int mat = lane >> 3;
    const uint32_t xorv = (uint32_t)(lane & 7) << 4;
    const int rA = (mat & 1) * 8 + (lane & 7);
    const int cA = (mat >> 1) * 16;
    const int rB = (mat >> 1) * 8 + (lane & 7);
    const int cB = (mat & 1) * 16;

    const int srow = tid >> 3, sci = tid & 7;
    float C[2][8][4] = {};

    #define PJ_STAGE_CHUNK(c) do {                                              \
        const int _k0 = (c) * 64;                                               \
        uint32_t _bb = sb + (uint32_t)((c) & 1) * PJ_STAGE;                     \
        _Pragma("unroll")                                                       \
        for (int _r = 0; _r < 4; _r++) {                                        \
            int _row = srow + _r * 32;                                          \
            uint32_t _doff = (uint32_t)_row * 128 +                             \
                (((uint32_t)sci * 16) ^ ((uint32_t)(_row & 7) << 4));           \
            const size_t _go = (size_t)(m0 + _row) * DD + _k0 + sci * 8;        \
            const size_t _gw = (size_t)_row * DD + _k0 + sci * 8;               \
            cp16(_bb + PJ_AH + _doff, xh + _go);                                \
            cp16(_bb + PJ_AL + _doff, xl + _go);                                \
            cp16(_bb + PJ_BH + _doff, wh + _gw);                                \
            cp16(_bb + PJ_BL + _doff, wl + _gw);                                \
        } } while (0)

    PJ_STAGE_CHUNK(0); CP_COMMIT();

    for (int c = 0; c < 16; c++) {
        if (c + 1 < 16) { PJ_STAGE_CHUNK(c + 1); CP_COMMIT(); CP_WAIT(1); }
        else            { CP_WAIT(0); }
        __syncthreads();
        const uint32_t bb = sb + (uint32_t)(c & 1) * PJ_STAGE;

        #pragma unroll
        for (int ks = 0; ks < 4; ks++) {
            const int k0 = ks * 16;
            uint32_t ah[2][4], al[2][4];
            #pragma unroll
            for (int mt = 0; mt < 2; mt++) {
                uint32_t aoff = (uint32_t)(mrow0 + mt*16 + rA) * 128 + (((uint32_t)(k0*2 + cA)) ^ xorv);
                ldm4(ah[mt], bb + PJ_AH + aoff);
                ldm4(al[mt], bb + PJ_AL + aoff);
            }
            #pragma unroll
            for (int nt2 = 0; nt2 < 4; nt2++) {
                const int n0 = ncol0 + nt2 * 16;
                uint32_t boff = (uint32_t)(n0 + rB) * 128 + (((uint32_t)(k0*2 + cB)) ^ xorv);
                uint32_t bh[4], bl[4];
                ldm4(bh, bb + PJ_BH + boff);
                ldm4(bl, bb + PJ_BL + boff);
                #pragma unroll
                for (int mt = 0; mt < 2; mt++) {
                    mma_f16(C[mt][nt2*2],   ah[mt], bh);
                    mma_f16(C[mt][nt2*2],   ah[mt], bl);
                    mma_f16(C[mt][nt2*2],   al[mt], bh);
                    mma_f16(C[mt][nt2*2+1], ah[mt], bh + 2);
                    mma_f16(C[mt][nt2*2+1], ah[mt], bl + 2);
                    mma_f16(C[mt][nt2*2+1], al[mt], bh + 2);
                }
            }
        }
        __syncthreads();
    }

    __half *dh, *dl;
    if (z == 0)      { dh = g_q_hi; dl = g_q_lo; }
    else if (z == 1) { dh = g_k_hi; dl = g_k_lo; }
    else             { dh = g_v_hi; dl = g_v_lo; }
    const int r = lane >> 2, c2 = 2 * (lane & 3);
    #pragma unroll
    for (int mt = 0; mt < 2; mt++) {
        #pragma unroll
        for (int nt = 0; nt < 8; nt++) {
            int cc = ncol0 + nt * 8 + c2;
            size_t mg0 = (size_t)(m0 + mrow0 + mt*16 + r);
            uint32_t h, l;
            split2(C[mt][nt][0], C[mt][nt][1], h, l);
            *(uint32_t*)(dh + mg0*QD + cc) = h;
            *(uint32_t*)(dl + mg0*QD + cc) = l;
            split2(C[mt][nt][2], C[mt][nt][3], h, l);
            *(uint32_t*)(dh + (mg0+8)*QD + cc) = h;
            *(uint32_t*)(dl + (mg0+8)*QD + cc) = l;
        }
    }
}

// ---------------- flash attention over COMPACTED keys ----------------
#define AT_QH 0
#define AT_QL 32768
#define AT_KH 65536
#define AT_KL 98304
#define AT_VH 131072
#define AT_VL 163840
#define AT_SMEM (196608 + 1024)

__global__ __launch_bounds__(256, 1) void attn_kernel(float* __restrict__ out)
{
    extern __shared__ char smraw[];
    char* sp = (char*)(((uintptr_t)smraw + 1023) & ~(uintptr_t)1023);
    uint32_t sb = smem_u32(sp);
    const int tid = threadIdx.x, lane = tid & 31, w = tid >> 5;
    const int b = blockIdx.y, t0 = blockIdx.x * 128;
    const int m0w = w * 16;

    const int mat = lane >> 3;
    const uint32_t xorv = (uint32_t)(lane & 7) << 4;
    const int rA = (mat & 1) * 8 + (lane & 7);
    const int cA = (mat >> 1) * 16;
    const int rB = (mat >> 1) * 8 + (lane & 7);
    const int cB = (mat & 1) * 16;

    const int srow = tid >> 4, sci = tid & 15;
    const int cnt = g_cnt[b];
    const int ntiles = (cnt + 127) >> 7;

    #define AT_ISSUE_K(it) do {                                                 \
        const int _s0 = (it) * 128;                                             \
        _Pragma("unroll")                                                       \
        for (int _r = 0; _r < 8; _r++) {                                        \
            int _row = srow + _r * 16;                                          \
            uint32_t _doff = (uint32_t)_row * 256 +                             \
                (((uint32_t)sci * 16) ^ ((uint32_t)(_row & 7) << 4));           \
            const size_t _g = (size_t)(b*TT + _s0 + _row) * QD + sci * 8;       \
            cp16(sb + AT_KH + _doff, g_kc_hi + _g);                             \
            cp16(sb + AT_KL + _doff, g_kc_lo + _g);                             \
        } } while (0)

    #define AT_ISSUE_V(it) do {                                                 \
        const int _s0 = (it) * 128;                                             \
        _Pragma("unroll")                                                       \
        for (int _r = 0; _r < 8; _r++) {                                        \
            int _row = srow + _r * 16;                                          \
            uint32_t _doff = (uint32_t)_row * 256 +                             \
                (((uint32_t)sci * 16) ^ ((uint32_t)(_row & 7) << 4));           \
            const size_t _g = (size_t)(b*TT + _s0 + _row) * QD + sci * 8;       \
            cp16(sb + AT_VH + _doff, g_vc_hi + _g);                             \
            cp16(sb + AT_VL + _doff, g_vc_lo + _g);                             \
        } } while (0)

    float O[16][4] = {};
    float m0r = -1.0e30f, m1r = -1.0e30f, s0r = 0.0f, s1r = 0.0f;
    const int c2 = 2 * (lane & 3);

    if (ntiles > 0) {
        AT_ISSUE_K(0); CP_COMMIT();
        AT_ISSUE_V(0); CP_COMMIT();

        const uint4* qh = (const uint4*)(g_q_hi + (size_t)(b*TT + t0) * QD);
        const uint4* ql = (const uint4*)(g_q_lo + (size_t)(b*TT + t0) * QD);
        #pragma unroll
        for (int r = 0; r < 8; r++) {
            int idx = tid + r * 256;
            int row = idx >> 4;
            uint32_t cb = (uint32_t)(idx & 15) * 16;
            uint32_t doff = (uint32_t)row * 256 + (cb ^ ((uint32_t)(row & 7) << 4));
            *(uint4*)(sp + AT_QH + doff) = qh[idx];
            *(uint4*)(sp + AT_QL + doff) = ql[idx];
        }

        for (int it = 0; it < ntiles; it++) {
            CP_WAIT(1);
            __syncthreads();

            float S[16][4] = {};
            #pragma unroll
            for (int ks = 0; ks < 8; ks++) {
                const int k0 = ks * 16;
                uint32_t aqh[4], aql[4];
                uint32_t aoff = (uint32_t)(m0w + rA) * 256 + (((uint32_t)(k0*2 + cA)) ^ xorv);
                ldm4(aqh, sb + AT_QH + aoff);
                ldm4(aql, sb + AT_QL + aoff);
                #pragma unroll
                for (int nt2 = 0; nt2 < 8; nt2++) {
                    const int n0 = nt2 * 16;
                    uint32_t boff = (uint32_t)(n0 + rB) * 256 + (((uint32_t)(k0*2 + cB)) ^ xorv);
                    uint32_t bh[4], bl[4];
                    ldm4(bh, sb + AT_KH + boff);
                    ldm4(bl, sb + AT_KL + boff);
                    mma_f16(S[nt2*2],   aqh, bh);
                    mma_f16(S[nt2*2],   aqh, bl);
                    mma_f16(S[nt2*2],   aql, bh);
                    mma_f16(S[nt2*2+1], aqh, bh + 2);
                    mma_f16(S[nt2*2+1], aqh, bl + 2);
                    mma_f16(S[nt2*2+1], aql, bh + 2);
                }
            }

            const int base = it * 128;
            float mx0 = -3.0e38f, mx1 = -3.0e38f;
            #pragma unroll
            for (int nt = 0; nt < 16; nt++) {
                bool v0 = (base + nt*8 + c2)     < cnt;
                bool v1 = (base + nt*8 + c2 + 1) < cnt;
                S[nt][0] = v0 ? S[nt][0] : -3.0e38f;
                S[nt][1] = v1 ? S[nt][1] : -3.0e38f;
                S[nt][2] = v0 ? S[nt][2] : -3.0e38f;
                S[nt][3] = v1 ? S[nt][3] : -3.0e38f;
                mx0 = fmaxf(mx0, fmaxf(S[nt][0], S[nt][1]));
                mx1 = fmaxf(mx1, fmaxf(S[nt][2], S[nt][3]));
            }
            mx0 = fmaxf(mx0, __shfl_xor_sync(0xffffffffu, mx0, 1));
            mx0 = fmaxf(mx0, __shfl_xor_sync(0xffffffffu, mx0, 2));
            mx1 = fmaxf(mx1, __shfl_xor_sync(0xffffffffu, mx1, 1));
            mx1 = fmaxf(mx1, __shfl_xor_sync(0xffffffffu, mx1, 2));
            float mn0 = fmaxf(m0r, mx0), mn1 = fmaxf(m1r, mx1);
            float sc0 = __expf(m0r - mn0), sc1 = __expf(m1r - mn1);
            float sum0 = 0.0f, sum1 = 0.0f;
            #pragma unroll
            for (int nt = 0; nt < 16; nt++) {
                S[nt][0] = __expf(S[nt][0] - mn0);
                S[nt][1] = __expf(S[nt][1] - mn0);
                S[nt][2] = __expf(S[nt][2] - mn1);
                S[nt][3] = __expf(S[nt][3] - mn1);
                sum0 += S[nt][0] + S[nt][1];
                sum1 += S[nt][2] + S[nt][3];
            }
            sum0 += __shfl_xor_sync(0xffffffffu, sum0, 1);
            sum0 += __shfl_xor_sync(0xffffffffu, sum0, 2);
            sum1 += __shfl_xor_sync(0xffffffffu, sum1, 1);
            sum1 += __shfl_xor_sync(0xffffffffu, sum1, 2);
            s0r = s0r * sc0 + sum0;  s1r = s1r * sc1 + sum1;
            m0r = mn0;  m1r = mn1;

            __syncthreads();
            if (it + 1 < ntiles) { AT_ISSUE_K(it + 1); CP_COMMIT(); CP_WAIT(1); }
            else                 { CP_WAIT(0); }
            __syncthreads();

            #pragma unroll
            for (int nt = 0; nt < 16; nt++) {
                O[nt][0] *= sc0; O[nt][1] *= sc0;
                O[nt][2] *= sc1; O[nt][3] *= sc1;
            }

            #pragma unroll
            for (int ks = 0; ks < 8; ks++) {
                uint32_t ah[4];
                ah[0] = pk(__float2half_rn(S[2*ks][0]),   __float2half_rn(S[2*ks][1]));
                ah[1] = pk(__float2half_rn(S[2*ks][2]),   __float2half_rn(S[2*ks][3]));
                ah[2] = pk(__float2half_rn(S[2*ks+1][0]), __float2half_rn(S[2*ks+1][1]));
                ah[3] = pk(__float2half_rn(S[2*ks+1][2]), __float2half_rn(S[2*ks+1][3]));
                const int sv0 = ks * 16;
                #pragma unroll
                for (int nt2 = 0; nt2 < 8; nt2++) {
                    const int d0 = nt2 * 16;
                    uint32_t voff = (uint32_t)(sv0 + rA) * 256 + (((uint32_t)(d0*2 + cA)) ^ xorv);
                    uint32_t bvh[4], bvl[4];
                    ldm4t(bvh, sb + AT_VH + voff);
                    ldm4t(bvl, sb + AT_VL + voff);
                    mma_f16(O[nt2*2],   ah, bvh);
                    mma_f16(O[nt2*2],   ah, bvl);
                    mma_f16(O[nt2*2+1], ah, bvh + 2);
                    mma_f16(O[nt2*2+1], ah, bvl + 2);
                }
            }
            __syncthreads();
            if (it + 1 < ntiles) { AT_ISSUE_V(it + 1); CP_COMMIT(); }
        }
    }

    const float inv0 = (s0r > 0.0f) ? 1.0f / s0r : 0.0f;
    const float inv1 = (s1r > 0.0f) ? 1.0f / s1r : 0.0f;
    const size_t row0 = (size_t)b*TT + t0 + m0w + (lane >> 2);
    #pragma unroll
    for (int nt = 0; nt < 16; nt++) {
        int col = nt * 8 + c2;
        *(float2*)(out + row0*QD + col)     = make_float2(O[nt][0]*inv0, O[nt][1]*inv0);
        *(float2*)(out + (row0+8)*QD + col) = make_float2(O[nt][2]*inv1, O[nt][3]*inv1);
    }
}

// ---------------- launch ----------------
extern "C" void kernel_launch(void* const* d_in, const int* in_sizes, int n_in,
                              void* d_out, int out_size)
{
    const float* x  = (const float*)d_in[0];
    const void*  mk = d_in[1];
    const float* Wq = (const float*)d_in[2];
    const float* Wk = (const float*)d_in[3];
    const float* Wv = (const float*)d_in[4];
    float* out = (float*)d_out;
    (void)in_sizes; (void)n_in; (void)out_size;

    // fused mask pipeline (sniff + expand + scan + zerotail)
    mask_scan_kernel<<<BB, 1024>>>((const uint8_t*)mk);

    // hi/lo splits
    prep_x_kernel<<<(int)((size_t)BB*TT*DD/8/256), 256>>>(x);
    dim3 gw(QD*DD/8/256, 3);
    prep_w_kernel<<<gw, 256>>>(Wq, Wk, Wv);

    cudaFuncSetAttribute(proj_kernel, cudaFuncAttributeMaxDynamicSharedMemorySize, PJ_SMEM);
    cudaFuncSetAttribute(attn_kernel, cudaFuncAttributeMaxDynamicSharedMemorySize, AT_SMEM);

    dim3 g1(128, 3);
    proj_kernel<<<g1, 256, PJ_SMEM>>>();

    dim3 gg(TT/4, BB);
    gather_kernel<<<gg, 256>>>();

    dim3 g2(TT/128, BB);
    attn_kernel<<<g2, 256, AT_SMEM>>>(out);
}

// round 17
// speedup vs baseline: 1.5775x; 1.0065x over previous
#include <cuda_runtime.h>
#include <cuda_fp16.h>
#include <cstdint>

#define BB 8
#define TT 2048
#define DD 1024
#define QD 128

// ---------------- global scratch (fp16 hi/lo splits) ----------------
__device__ __half g_x_hi[(size_t)BB*TT*DD];
__device__ __half g_x_lo[(size_t)BB*TT*DD];
__device__ __half g_w_hi[3*QD*DD];
__device__ __half g_w_lo[3*QD*DD];
__device__ __half g_q_hi[BB*TT*QD];
__device__ __half g_q_lo[BB*TT*QD];
__device__ __half g_k_hi[BB*TT*QD];
__device__ __half g_k_lo[BB*TT*QD];
__device__ __half g_v_hi[BB*TT*QD];
__device__ __half g_v_lo[BB*TT*QD];
// compacted (unmasked) K/V rows, per batch
__device__ __half g_kc_hi[BB*TT*QD];
__device__ __half g_kc_lo[BB*TT*QD];
__device__ __half g_vc_hi[BB*TT*QD];
__device__ __half g_vc_lo[BB*TT*QD];
__device__ int   g_pos[BB*TT];
__device__ int   g_cnt[BB];
__device__ float g_mask[BB*TT];

// ---------------- helpers ----------------
__device__ __forceinline__ uint32_t smem_u32(const void* p) {
    uint32_t a;
    asm("{ .reg .u64 t; cvta.to.shared.u64 t, %1; cvt.u32.u64 %0, t; }" : "=r"(a) : "l"(p));
    return a;
}
__device__ __forceinline__ uint32_t pk(__half a, __half b) {
    return (uint32_t)__half_as_ushort(a) | ((uint32_t)__half_as_ushort(b) << 16);
}
__device__ __forceinline__ void split2(float a, float b, uint32_t& h, uint32_t& l) {
    __half ha = __float2half_rn(a);
    __half hb = __float2half_rn(b);
    __half la = __float2half_rn(a - __half2float(ha));
    __half lb = __float2half_rn(b - __half2float(hb));
    h = pk(ha, hb); l = pk(la, lb);
}
__device__ __forceinline__ void ldm4(uint32_t r[4], uint32_t a) {
    asm volatile("ldmatrix.sync.aligned.m8n8.x4.shared.b16 {%0,%1,%2,%3}, [%4];"
        : "=r"(r[0]), "=r"(r[1]), "=r"(r[2]), "=r"(r[3]) : "r"(a));
}
__device__ __forceinline__ void ldm4t(uint32_t r[4], uint32_t a) {
    asm volatile("ldmatrix.sync.aligned.m8n8.x4.trans.shared.b16 {%0,%1,%2,%3}, [%4];"
        : "=r"(r[0]), "=r"(r[1]), "=r"(r[2]), "=r"(r[3]) : "r"(a));
}
__device__ __forceinline__ void mma_f16(float* c, const uint32_t* a, const uint32_t* b) {
    asm volatile("mma.sync.aligned.m16n8k16.row.col.f32.f16.f16.f32 "
        "{%0,%1,%2,%3}, {%4,%5,%6,%7}, {%8,%9}, {%0,%1,%2,%3};"
        : "+f"(c[0]), "+f"(c[1]), "+f"(c[2]), "+f"(c[3])
        : "r"(a[0]), "r"(a[1]), "r"(a[2]), "r"(a[3]), "r"(b[0]), "r"(b[1]));
}
__device__ __forceinline__ void cp16(uint32_t dst, const void* src) {
    asm volatile("cp.async.cg.shared.global [%0], [%1], 16;"
        :: "r"(dst), "l"(__cvta_generic_to_global(src)) : "memory");
}
#define CP_COMMIT() asm volatile("cp.async.commit_group;" ::: "memory")
#define CP_WAIT(n)  asm volatile("cp.async.wait_group %0;" :: "n"(n) : "memory")

// ---------------- fused mask pipeline: sniff + expand + scan + zerotail ----------------
__global__ __launch_bounds__(1024) void mask_scan_kernel(const uint8_t* __restrict__ m)
{
    __shared__ int sc[1024];
    __shared__ unsigned red[64];
    const int b = blockIdx.x, tid = threadIdx.x;

    unsigned o1 = 0, o3 = 0;
    if (tid < 512) {
        uint32_t v = ((const uint32_t*)m)[b*512 + tid];
        o1 = (v >> 8) & 0xFFu; o3 = (v >> 24) & 0xFFu;
    }
    #pragma unroll
    for (int off = 16; off; off >>= 1) {
        o1 |= __shfl_xor_sync(0xffffffffu, o1, off);
        o3 |= __shfl_xor_sync(0xffffffffu, o3, off);
    }
    if ((tid & 31) == 0) { red[(tid>>5)*2] = o1; red[(tid>>5)*2 + 1] = o3; }
    __syncthreads();
    if (tid == 0) {
        unsigned a1 = 0, a3 = 0;
        for (int i = 0; i < 32; i++) { a1 |= red[i*2]; a3 |= red[i*2+1]; }
        red[0] = a1 ? 1u : (a3 ? 2u : 0u);
    }
    __syncthreads();
    const int kind = (int)red[0];

    const int s0 = b*TT + 2*tid;
    int e0, e1;
    if (kind == 1)      { e0 = m[s0] != 0;                      e1 = m[s0+1] != 0; }
    else if (kind == 2) { e0 = ((const float*)m)[s0] != 0.0f;   e1 = ((const float*)m)[s0+1] != 0.0f; }
    else                { e0 = ((const int*)m)[s0] != 0;        e1 = ((const int*)m)[s0+1] != 0; }
    g_mask[s0]     = e0 ? 1.0f : 0.0f;
    g_mask[s0 + 1] = e1 ? 1.0f : 0.0f;

    int part = e0 + e1;
    sc[tid] = part;
    __syncthreads();
    for (int off = 1; off < 1024; off <<= 1) {
        int v = (tid >= off) ? sc[tid - off] : 0;
        __syncthreads();
        sc[tid] += v;
        __syncthreads();
    }
    int excl = sc[tid] - part;
    g_pos[s0]     = excl;
    g_pos[s0 + 1] = excl + e0;
    const int cnt = sc[1023];
    if (tid == 1023) g_cnt[b] = cnt;

    const int end = (cnt + 127) & ~127;
    const uint4 z = make_uint4(0, 0, 0, 0);
    for (int i = tid; i < (end - cnt) * 16; i += 1024) {
        int r = cnt + (i >> 4), ch = i & 15;
        size_t base = (size_t)(b*TT + r) * QD;
        *((uint4*)(g_kc_hi + base) + ch) = z;
        *((uint4*)(g_kc_lo + base) + ch) = z;
        *((uint4*)(g_vc_hi + base) + ch) = z;
        *((uint4*)(g_vc_lo + base) + ch) = z;
    }
}

// ---------------- gather unmasked K/V rows ----------------
__global__ __launch_bounds__(256) void gather_kernel() {
    const int b = blockIdx.y;
    const int row = blockIdx.x * 4 + (threadIdx.x >> 6);
    const int c = threadIdx.x & 63;
    if (g_mask[b*TT + row] == 0.0f) return;
    const int dst = g_pos[b*TT + row];
    const int a = c >> 4, ch = c & 15;
    const __half* src = (a == 0) ? g_k_hi : (a == 1) ? g_k_lo : (a == 2) ? g_v_hi : g_v_lo;
    __half*       dp  = (a == 0) ? g_kc_hi : (a == 1) ? g_kc_lo : (a == 2) ? g_vc_hi : g_vc_lo;
    *((uint4*)(dp + (size_t)(b*TT + dst)*QD) + ch) =
        *((const uint4*)(src + (size_t)(b*TT + row)*QD) + ch);
}

// ---------------- prep: split x / W into fp16 hi/lo ----------------
__global__ __launch_bounds__(256) void prep_x_kernel(const float* __restrict__ x) {
    const size_t i = (size_t)blockIdx.x * 256 + threadIdx.x;
    const float4* s = (const float4*)x;
    float4 a = s[2*i], c = s[2*i + 1];
    uint32_t h0,l0,h1,l1,h2,l2,h3,l3;
    split2(a.x, a.y, h0, l0); split2(a.z, a.w, h1, l1);
    split2(c.x, c.y, h2, l2); split2(c.z, c.w, h3, l3);
    ((uint4*)g_x_hi)[i] = make_uint4(h0, h1, h2, h3);
    ((uint4*)g_x_lo)[i] = make_uint4(l0, l1, l2, l3);
}
__global__ __launch_bounds__(256) void prep_w_kernel(
    const float* __restrict__ Wq, const float* __restrict__ Wk,
    const float* __restrict__ Wv)
{
    const int z = blockIdx.y;
    const float* W = (z == 0) ? Wq : (z == 1) ? Wk : Wv;
    const size_t i = (size_t)blockIdx.x * 256 + threadIdx.x;
    const float4* s = (const float4*)W;
    float4 a = s[2*i], c = s[2*i + 1];
    uint32_t h0,l0,h1,l1,h2,l2,h3,l3;
    split2(a.x, a.y, h0, l0); split2(a.z, a.w, h1, l1);
    split2(c.x, c.y, h2, l2); split2(c.z, c.w, h3, l3);
    const size_t off = (size_t)z * QD * DD / 8;
    ((uint4*)g_w_hi)[off + i] = make_uint4(h0, h1, h2, h3);
    ((uint4*)g_w_lo)[off + i] = make_uint4(l0, l1, l2, l3);
}

// ---------------- projection GEMM (fp16x3, cp.async, fragment double-buffer) ----------------
#define PJ_AH 0
#define PJ_AL 16384
#define PJ_BH 32768
#define PJ_BL 49152
#define PJ_STAGE 65536
#define PJ_SMEM (2*PJ_STAGE + 1024)

__global__ __launch_bounds__(256, 1) void proj_kernel()
{
    extern __shared__ char smraw[];
    char* sp = (char*)(((uintptr_t)smraw + 1023) & ~(uintptr_t)1023);
    uint32_t sb = smem_u32(sp);
    const int tid = threadIdx.x, lane = tid & 31, w = tid >> 5;
    const int m0 = blockIdx.x * 128, z = blockIdx.y;
    const int wm = w & 3, wn = w >> 2;
    const int mrow0 = wm * 32, ncol0 = wn * 64;

    const __half* xh = g_x_hi;
    const __half* xl = g_x_lo;
    const __half* wh = g_w_hi + (size_t)z*QD*DD;
    const __half* wl = g_w_lo + (size_t)z*QD*DD;

    const int mat = lane >> 3;
    const uint32_t xorv = (uint32_t)(lane & 7) << 4;
    const int rA = (mat & 1) * 8 + (lane & 7);
    const int cA = (mat >> 1) * 16;
    const int rB = (mat >> 1) * 8 + (lane & 7);
    const int cB = (mat & 1) * 16;

    const int srow = tid >> 3, sci = tid & 7;
    float C[2][8][4] = {};

    #define PJ_STAGE_CHUNK(c) do {                                              \
        const int _k0 = (c) * 64;                                               \
        uint32_t _bb = sb + (uint32_t)((c) & 1) * PJ_STAGE;                     \
        _Pragma("unroll")                                                       \
        for (int _r = 0; _r < 4; _r++) {                                        \
            int _row = srow + _r * 32;                                          \
            uint32_t _doff = (uint32_t)_row * 128 +                             \
                (((uint32_t)sci * 16) ^ ((uint32_t)(_row & 7) << 4));           \
            const size_t _go = (size_t)(m0 + _row) * DD + _k0 + sci * 8;        \
            const size_t _gw = (size_t)_row * DD + _k0 + sci * 8;               \
            cp16(_bb + PJ_AH + _doff, xh + _go);                                \
            cp16(_bb + PJ_AL + _doff, xl + _go);                                \
            cp16(_bb + PJ_BH + _doff, wh + _gw);                                \
            cp16(_bb + PJ_BL + _doff, wl + _gw);                                \
        } } while (0)

    // fragment loads (register double-buffered)
    #define PJ_LOADA(ks, buf) do {                                              \
        const int _k0 = (ks) * 16;                                              \
        _Pragma("unroll")                                                       \
        for (int _mt = 0; _mt < 2; _mt++) {                                     \
            uint32_t _aoff = (uint32_t)(mrow0 + _mt*16 + rA) * 128 +            \
                (((uint32_t)(_k0*2 + cA)) ^ xorv);                              \
            ldm4(ah[buf][_mt], bbase + PJ_AH + _aoff);                          \
            ldm4(al[buf][_mt], bbase + PJ_AL + _aoff);                          \
        } } while (0)
    #define PJ_LOADB(ks, nt2, buf) do {                                         \
        const int _k0 = (ks) * 16;                                              \
        const int _n0 = ncol0 + (nt2) * 16;                                     \
        uint32_t _boff = (uint32_t)(_n0 + rB) * 128 +                           \
            (((uint32_t)(_k0*2 + cB)) ^ xorv);                                  \
        ldm4(bh[buf], bbase + PJ_BH + _boff);                                   \
        ldm4(bl[buf], bbase + PJ_BL + _boff);                                   \
    } while (0)

    PJ_STAGE_CHUNK(0); CP_COMMIT();

    for (int c = 0; c < 16; c++) {
        if (c + 1 < 16) { PJ_STAGE_CHUNK(c + 1); CP_COMMIT(); CP_WAIT(1); }
        else            { CP_WAIT(0); }
        __syncthreads();
        const uint32_t bbase = sb + (uint32_t)(c & 1) * PJ_STAGE;

        uint32_t ah[2][2][4], al[2][2][4];   // [buf][mt][4]
        uint32_t bh[2][4], bl[2][4];          // [buf][4]
        PJ_LOADA(0, 0);
        PJ_LOADB(0, 0, 0);

        #pragma unroll
        for (int ks = 0; ks < 4; ks++) {
            const int abuf = ks & 1;
            if (ks < 3) PJ_LOADA(ks + 1, abuf ^ 1);   // prefetch next A under MMAs
            #pragma unroll
            for (int nt2 = 0; nt2 < 4; nt2++) {
                const int bbuf = (ks * 4 + nt2) & 1;
                // prefetch next B fragments before consuming current
                if (nt2 < 3)      PJ_LOADB(ks, nt2 + 1, bbuf ^ 1);
                else if (ks < 3)  PJ_LOADB(ks + 1, 0,   bbuf ^ 1);
                #pragma unroll
                for (int mt = 0; mt < 2; mt++) {
                    mma_f16(C[mt][nt2*2],   ah[abuf][mt], bh[bbuf]);
                    mma_f16(C[mt][nt2*2],   ah[abuf][mt], bl[bbuf]);
                    mma_f16(C[mt][nt2*2],   al[abuf][mt], bh[bbuf]);
                    mma_f16(C[mt][nt2*2+1], ah[abuf][mt], bh[bbuf] + 2);
                    mma_f16(C[mt][nt2*2+1], ah[abuf][mt], bl[bbuf] + 2);
                    mma_f16(C[mt][nt2*2+1], al[abuf][mt], bh[bbuf] + 2);
                }
            }
        }
        __syncthreads();
    }

    __half *dh, *dl;
    if (z == 0)      { dh = g_q_hi; dl = g_q_lo; }
    else if (z == 1) { dh = g_k_hi; dl = g_k_lo; }
    else             { dh = g_v_hi; dl = g_v_lo; }
    const int r = lane >> 2, c2 = 2 * (lane & 3);
    #pragma unroll
    for (int mt = 0; mt < 2; mt++) {
        #pragma unroll
        for (int nt = 0; nt < 8; nt++) {
            int cc = ncol0 + nt * 8 + c2;
            size_t mg0 = (size_t)(m0 + mrow0 + mt*16 + r);
            uint32_t h, l;
            split2(C[mt][nt][0], C[mt][nt][1], h, l);
            *(uint32_t*)(dh + mg0*QD + cc) = h;
            *(uint32_t*)(dl + mg0*QD + cc) = l;
            split2(C[mt][nt][2], C[mt][nt][3], h, l);
            *(uint32_t*)(dh + (mg0+8)*QD + cc) = h;
            *(uint32_t*)(dl + (mg0+8)*QD + cc) = l;
        }
    }
}

// ---------------- flash attention over COMPACTED keys (unchanged R16 winner) ----------------
#define AT_QH 0
#define AT_QL 32768
#define AT_KH 65536
#define AT_KL 98304
#define AT_VH 131072
#define AT_VL 163840
#define AT_SMEM (196608 + 1024)

__global__ __launch_bounds__(256, 1) void attn_kernel(float* __restrict__ out)
{
    extern __shared__ char smraw[];
    char* sp = (char*)(((uintptr_t)smraw + 1023) & ~(uintptr_t)1023);
    uint32_t sb = smem_u32(sp);
    const int tid = threadIdx.x, lane = tid & 31, w = tid >> 5;
    const int b = blockIdx.y, t0 = blockIdx.x * 128;
    const int m0w = w * 16;

    const int mat = lane >> 3;
    const uint32_t xorv = (uint32_t)(lane & 7) << 4;
    const int rA = (mat & 1) * 8 + (lane & 7);
    const int cA = (mat >> 1) * 16;
    const int rB = (mat >> 1) * 8 + (lane & 7);
    const int cB = (mat & 1) * 16;

    const int srow = tid >> 4, sci = tid & 15;
    const int cnt = g_cnt[b];
    const int ntiles = (cnt + 127) >> 7;

    #define AT_ISSUE_K(it) do {                                                 \
        const int _s0 = (it) * 128;                                             \
        _Pragma("unroll")                                                       \
        for (int _r = 0; _r < 8; _r++) {                                        \
            int _row = srow + _r * 16;                                          \
            uint32_t _doff = (uint32_t)_row * 256 +                             \
                (((uint32_t)sci * 16) ^ ((uint32_t)(_row & 7) << 4));           \
            const size_t _g = (size_t)(b*TT + _s0 + _row) * QD + sci * 8;       \
            cp16(sb + AT_KH + _doff, g_kc_hi + _g);                             \
            cp16(sb + AT_KL + _doff, g_kc_lo + _g);                             \
        } } while (0)

    #define AT_ISSUE_V(it) do {                                                 \
        const int _s0 = (it) * 128;                                             \
        _Pragma("unroll")                                                       \
        for (int _r = 0; _r < 8; _r++) {                                        \
            int _row = srow + _r * 16;                                          \
            uint32_t _doff = (uint32_t)_row * 256 +                             \
                (((uint32_t)sci * 16) ^ ((uint32_t)(_row & 7) << 4));           \
            const size_t _g = (size_t)(b*TT + _s0 + _row) * QD + sci * 8;       \
            cp16(sb + AT_VH + _doff, g_vc_hi + _g);                             \
            cp16(sb + AT_VL + _doff, g_vc_lo + _g);                             \
        } } while (0)

    float O[16][4] = {};
    float m0r = -1.0e30f, m1r = -1.0e30f, s0r = 0.0f, s1r = 0.0f;
    const int c2 = 2 * (lane & 3);

    if (ntiles > 0) {
        AT_ISSUE_K(0); CP_COMMIT();
        AT_ISSUE_V(0); CP_COMMIT();

        const uint4* qh = (const uint4*)(g_q_hi + (size_t)(b*TT + t0) * QD);
        const uint4* ql = (const uint4*)(g_q_lo + (size_t)(b*TT + t0) * QD);
        #pragma unroll
        for (int r = 0; r < 8; r++) {
            int idx = tid + r * 256;
            int row = idx >> 4;
            uint32_t cb = (uint32_t)(idx & 15) * 16;
            uint32_t doff = (uint32_t)row * 256 + (cb ^ ((uint32_t)(row & 7) << 4));
            *(uint4*)(sp + AT_QH + doff) = qh[idx];
            *(uint4*)(sp + AT_QL + doff) = ql[idx];
        }

        for (int it = 0; it < ntiles; it++) {
            CP_WAIT(1);
            __syncthreads();

            float S[16][4] = {};
            #pragma unroll
            for (int ks = 0; ks < 8; ks++) {
                const int k0 = ks * 16;
                uint32_t aqh[4], aql[4];
                uint32_t aoff = (uint32_t)(m0w + rA) * 256 + (((uint32_t)(k0*2 + cA)) ^ xorv);
                ldm4(aqh, sb + AT_QH + aoff);
                ldm4(aql, sb + AT_QL + aoff);
                #pragma unroll
                for (int nt2 = 0; nt2 < 8; nt2++) {
                    const int n0 = nt2 * 16;
                    uint32_t boff = (uint32_t)(n0 + rB) * 256 + (((uint32_t)(k0*2 + cB)) ^ xorv);
                    uint32_t bh[4], bl[4];
                    ldm4(bh, sb + AT_KH + boff);
                    ldm4(bl, sb + AT_KL + boff);
                    mma_f16(S[nt2*2],   aqh, bh);
                    mma_f16(S[nt2*2],   aqh, bl);
                    mma_f16(S[nt2*2],   aql, bh);
                    mma_f16(S[nt2*2+1], aqh, bh + 2);
                    mma_f16(S[nt2*2+1], aqh, bl + 2);
                    mma_f16(S[nt2*2+1], aql, bh + 2);
                }
            }

            const int base = it * 128;
            float mx0 = -3.0e38f, mx1 = -3.0e38f;
            #pragma unroll
            for (int nt = 0; nt < 16; nt++) {
                bool v0 = (base + nt*8 + c2)     < cnt;
                bool v1 = (base + nt*8 + c2 + 1) < cnt;
                S[nt][0] = v0 ? S[nt][0] : -3.0e38f;
                S[nt][1] = v1 ? S[nt][1] : -3.0e38f;
                S[nt][2] = v0 ? S[nt][2] : -3.0e38f;
                S[nt][3] = v1 ? S[nt][3] : -3.0e38f;
                mx0 = fmaxf(mx0, fmaxf(S[nt][0], S[nt][1]));
                mx1 = fmaxf(mx1, fmaxf(S[nt][2], S[nt][3]));
            }
            mx0 = fmaxf(mx0, __shfl_xor_sync(0xffffffffu, mx0, 1));
            mx0 = fmaxf(mx0, __shfl_xor_sync(0xffffffffu, mx0, 2));
            mx1 = fmaxf(mx1, __shfl_xor_sync(0xffffffffu, mx1, 1));
            mx1 = fmaxf(mx1, __shfl_xor_sync(0xffffffffu, mx1, 2));
            float mn0 = fmaxf(m0r, mx0), mn1 = fmaxf(m1r, mx1);
            float sc0 = __expf(m0r - mn0), sc1 = __expf(m1r - mn1);
            float sum0 = 0.0f, sum1 = 0.0f;
            #pragma unroll
            for (int nt = 0; nt < 16; nt++) {
                S[nt][0] = __expf(S[nt][0] - mn0);
                S[nt][1] = __expf(S[nt][1] - mn0);
                S[nt][2] = __expf(S[nt][2] - mn1);
                S[nt][3] = __expf(S[nt][3] - mn1);
                sum0 += S[nt][0] + S[nt][1];
                sum1 += S[nt][2] + S[nt][3];
            }
            sum0 += __shfl_xor_sync(0xffffffffu, sum0, 1);
            sum0 += __shfl_xor_sync(0xffffffffu, sum0, 2);
            sum1 += __shfl_xor_sync(0xffffffffu, sum1, 1);
            sum1 += __shfl_xor_sync(0xffffffffu, sum1, 2);
            s0r = s0r * sc0 + sum0;  s1r = s1r * sc1 + sum1;
            m0r = mn0;  m1r = mn1;

            __syncthreads();
            if (it + 1 < ntiles) { AT_ISSUE_K(it + 1); CP_COMMIT(); CP_WAIT(1); }
            else                 { CP_WAIT(0); }
            __syncthreads();

            #pragma unroll
            for (int nt = 0; nt < 16; nt++) {
                O[nt][0] *= sc0; O[nt][1] *= sc0;
                O[nt][2] *= sc1; O[nt][3] *= sc1;
            }

            #pragma unroll
            for (int ks = 0; ks < 8; ks++) {
                uint32_t ah[4];
                ah[0] = pk(__float2half_rn(S[2*ks][0]),   __float2half_rn(S[2*ks][1]));
                ah[1] = pk(__float2half_rn(S[2*ks][2]),   __float2half_rn(S[2*ks][3]));
                ah[2] = pk(__float2half_rn(S[2*ks+1][0]), __float2half_rn(S[2*ks+1][1]));
                ah[3] = pk(__float2half_rn(S[2*ks+1][2]), __float2half_rn(S[2*ks+1][3]));
                const int sv0 = ks * 16;
                #pragma unroll
                for (int nt2 = 0; nt2 < 8; nt2++) {
                    const int d0 = nt2 * 16;
                    uint32_t voff = (uint32_t)(sv0 + rA) * 256 + (((uint32_t)(d0*2 + cA)) ^ xorv);
                    uint32_t bvh[4], bvl[4];
                    ldm4t(bvh, sb + AT_VH + voff);
                    ldm4t(bvl, sb + AT_VL + voff);
                    mma_f16(O[nt2*2],   ah, bvh);
                    mma_f16(O[nt2*2],   ah, bvl);
                    mma_f16(O[nt2*2+1], ah, bvh + 2);
                    mma_f16(O[nt2*2+1], ah, bvl + 2);
                }
            }
            __syncthreads();
            if (it + 1 < ntiles) { AT_ISSUE_V(it + 1); CP_COMMIT(); }
        }
    }

    const float inv0 = (s0r > 0.0f) ? 1.0f / s0r : 0.0f;
    const float inv1 = (s1r > 0.0f) ? 1.0f / s1r : 0.0f;
    const size_t row0 = (size_t)b*TT + t0 + m0w + (lane >> 2);
    #pragma unroll
    for (int nt = 0; nt < 16; nt++) {
        int col = nt * 8 + c2;
        *(float2*)(out + row0*QD + col)     = make_float2(O[nt][0]*inv0, O[nt][1]*inv0);
        *(float2*)(out + (row0+8)*QD + col) = make_float2(O[nt][2]*inv1, O[nt][3]*inv1);
    }
}

// ---------------- launch ----------------
extern "C" void kernel_launch(void* const* d_in, const int* in_sizes, int n_in,
                              void* d_out, int out_size)
{
    const float* x  = (const float*)d_in[0];
    const void*  mk = d_in[1];
    const float* Wq = (const float*)d_in[2];
    const float* Wk = (const float*)d_in[3];
    const float* Wv = (const float*)d_in[4];
    float* out = (float*)d_out;
    (void)in_sizes; (void)n_in; (void)out_size;

    mask_scan_kernel<<<BB, 1024>>>((const uint8_t*)mk);

    prep_x_kernel<<<(int)((size_t)BB*TT*DD/8/256), 256>>>(x);
    dim3 gw(QD*DD/8/256, 3);
    prep_w_kernel<<<gw, 256>>>(Wq, Wk, Wv);

    cudaFuncSetAttribute(proj_kernel, cudaFuncAttributeMaxDynamicSharedMemorySize, PJ_SMEM);
    cudaFuncSetAttribute(attn_kernel, cudaFuncAttributeMaxDynamicSharedMemorySize, AT_SMEM);

    dim3 g1(128, 3);
    proj_kernel<<<g1, 256, PJ_SMEM>>>();

    dim3 gg(TT/4, BB);
    gather_kernel<<<gg, 256>>>();

    dim3 g2(TT/128, BB);
    attn_kernel<<<g2, 256, AT_SMEM>>>(out);
}